// round 14
// baseline (speedup 1.0000x reference)
#include <cuda_runtime.h>
#include <cuda_bf16.h>
#include <math.h>
#include <stdint.h>

// ---------------- problem constants ----------------
#define BATCH   64
#define HH      56
#define WW_DIM  56
#define CC      128
#define WIN     7
#define SHIFT   3
#define NH      4
#define HD      32
#define NTOK    49
#define TOTW    (BATCH*64)      // 4096 windows
#define MROWS   (TOTW*NTOK)     // 200704 token rows
#define MLPH    512

// ---------------- scratch ----------------
__device__ __nv_bfloat16 g_hwin[(size_t)MROWS*CC];
__device__ __nv_bfloat16 g_qkv [(size_t)MROWS*3*CC];
__device__ __nv_bfloat16 g_obuf[(size_t)MROWS*CC];
__device__ float         g_x1  [(size_t)MROWS*CC];
__device__ __nv_bfloat16 g_wq [3*CC*CC];
__device__ __nv_bfloat16 g_wp [CC*CC];
__device__ __nv_bfloat16 g_wf1[MLPH*CC];
__device__ __nv_bfloat16 g_wf2[CC*MLPH];
__device__ float g_bq[3*CC];
__device__ __nv_bfloat16 g_bm[4*4*64*64];

__device__ __forceinline__ int win_to_img(int grow) {
    int w = grow / NTOK, n = grow - w * NTOK;
    int bi = w >> 6, widx = w & 63;
    int r = ((widx >> 3) * WIN + n / WIN + SHIFT) % HH;
    int c = ((widx & 7)  * WIN + n % WIN + SHIFT) % WW_DIM;
    return bi * (HH * WW_DIM) + r * WW_DIM + c;
}

#define QSCALE 0.17677669529663687f

// ------- weights fp32 -> bf16 (+ fold q scale) + bias/mask table, 1 launch --
__global__ void f2bf_all(const float* __restrict__ w0, const float* __restrict__ w1,
                         const float* __restrict__ w2, const float* __restrict__ w3,
                         const float* __restrict__ qb, const float* __restrict__ rpb,
                         __nv_bfloat16* o0, __nv_bfloat16* o1,
                         __nv_bfloat16* o2, __nv_bfloat16* o3,
                         float* bq, __nv_bfloat16* bm)
{
    int i = blockIdx.x * 256 + threadIdx.x;
    if (i < 49152) {
        float v = w0[i];
        if (i < 16384) v *= QSCALE;
        o0[i] = __float2bfloat16_rn(v);
    }
    else if (i < 65536)  o1[i - 49152]  = __float2bfloat16_rn(w1[i - 49152]);
    else if (i < 131072) o2[i - 65536]  = __float2bfloat16_rn(w2[i - 65536]);
    else                 o3[i - 131072] = __float2bfloat16_rn(w3[i - 131072]);
    if (i < 384) bq[i] = qb[i] * (i < 128 ? QSCALE : 1.f);

    if (i < 65536) {
        int m = i & 63, n = (i >> 6) & 63, h = (i >> 12) & 3, wt = i >> 14;
        float v;
        if (m >= NTOK) v = -1e30f;
        else {
            int ne = n < NTOK ? n : NTOK - 1;
            int ny = ne / 7, nx = ne % 7, my = m / 7, mx = m % 7;
            v = rpb[((ny - my + 6) * 13 + (nx - mx + 6)) * NH + h];
            int wh7 = wt >> 1, ww7 = wt & 1;
            int lrn = wh7 ? (ny < 4 ? 1 : 2) : 0;
            int lcn = ww7 ? (nx < 4 ? 1 : 2) : 0;
            int lrm = wh7 ? (my < 4 ? 1 : 2) : 0;
            int lcm = ww7 ? (mx < 4 ? 1 : 2) : 0;
            if (lrn * 3 + lcn != lrm * 3 + lcm) v -= 100.f;
        }
        bm[i] = __float2bfloat16_rn(v);
    }
}

// ---------------- HMMA / cp.async helpers ----------------
__device__ __forceinline__ void ldsm4(uint32_t &r0, uint32_t &r1, uint32_t &r2, uint32_t &r3, uint32_t addr) {
    asm volatile("ldmatrix.sync.aligned.m8n8.x4.shared.b16 {%0,%1,%2,%3}, [%4];\n"
                 : "=r"(r0), "=r"(r1), "=r"(r2), "=r"(r3) : "r"(addr));
}
__device__ __forceinline__ void ldsm4t(uint32_t &r0, uint32_t &r1, uint32_t &r2, uint32_t &r3, uint32_t addr) {
    asm volatile("ldmatrix.sync.aligned.m8n8.x4.trans.shared.b16 {%0,%1,%2,%3}, [%4];\n"
                 : "=r"(r0), "=r"(r1), "=r"(r2), "=r"(r3) : "r"(addr));
}
__device__ __forceinline__ void mma16816(float c[4], uint32_t a0, uint32_t a1, uint32_t a2, uint32_t a3,
                                         uint32_t b0, uint32_t b1) {
    asm volatile("mma.sync.aligned.m16n8k16.row.col.f32.bf16.bf16.f32 "
                 "{%0,%1,%2,%3}, {%4,%5,%6,%7}, {%8,%9}, {%0,%1,%2,%3};\n"
                 : "+f"(c[0]), "+f"(c[1]), "+f"(c[2]), "+f"(c[3])
                 : "r"(a0), "r"(a1), "r"(a2), "r"(a3), "r"(b0), "r"(b1));
}
__device__ __forceinline__ uint32_t pack_bf2(float a, float b) {
    __nv_bfloat162 p = __floats2bfloat162_rn(a, b);
    return *(uint32_t*)&p;
}
__device__ __forceinline__ void cp16(uint32_t dst, const void* src) {
    asm volatile("cp.async.ca.shared.global [%0], [%1], 16;\n" :: "r"(dst), "l"(src));
}
#define CP_COMMIT() asm volatile("cp.async.commit_group;\n" ::: "memory")

// ============ full-K resident tiles (pitch 136) ============================
#define FP 136
#define TILE_B (128 * FP * 2)   // 34816 bytes

__device__ __forceinline__ void load_w136(uint32_t dst, const __nv_bfloat16* src,
                                          int ldk, int tid)
{
    #pragma unroll
    for (int i = 0; i < 8; i++) {
        int ch = i * 256 + tid;
        int r = ch >> 4, c8 = ch & 15;
        cp16(dst + (uint32_t)(r * FP + c8 * 8) * 2, src + (size_t)r * ldk + c8 * 8);
    }
}

// inline LayerNorm: 128 rows, warp per row, bf16 smem out
__device__ __forceinline__ void ln_to_smem(const float* __restrict__ in, uint32_t dstB,
    const float* __restrict__ g, const float* __restrict__ b,
    int blockM, int gather, int tid)
{
    int warp = tid >> 5, lane = tid & 31;
    float4 gg = *(const float4*)(g + lane * 4);
    float4 bb = *(const float4*)(b + lane * 4);
    #pragma unroll
    for (int i = 0; i < 16; i++) {
        int r = i * 8 + warp;
        int row = blockM + r;
        int src = gather ? win_to_img(row) : row;
        float4 v = *(const float4*)(in + (size_t)src * CC + lane * 4);
        float s = v.x + v.y + v.z + v.w;
        #pragma unroll
        for (int o = 16; o; o >>= 1) s += __shfl_xor_sync(~0u, s, o);
        float mean = s * (1.f / CC);
        float dx = v.x - mean, dy = v.y - mean, dz = v.z - mean, dw = v.w - mean;
        float vv = dx*dx + dy*dy + dz*dz + dw*dw;
        #pragma unroll
        for (int o = 16; o; o >>= 1) vv += __shfl_xor_sync(~0u, vv, o);
        float rstd = rsqrtf(vv * (1.f / CC) + 1e-5f);
        uint32_t p0 = pack_bf2(dx * rstd * gg.x + bb.x, dy * rstd * gg.y + bb.y);
        uint32_t p1 = pack_bf2(dz * rstd * gg.z + bb.z, dw * rstd * gg.w + bb.w);
        asm volatile("st.shared.v2.b32 [%0], {%1,%2};" ::
                     "r"(dstB + (uint32_t)(r * FP + lane * 4) * 2), "r"(p0), "r"(p1) : "memory");
    }
}

// full-K (128) warp-tile MMA on pitch-136 smem: 32x64 warp tile
__device__ __forceinline__ void wtile_mma(uint32_t aB, uint32_t bB, float acc[2][8][4],
                                          int warp_m, int warp_n, int rowin, int kin)
{
    #pragma unroll
    for (int ks = 0; ks < 128; ks += 16) {
        uint32_t af[2][4], bfr[4][4];
        #pragma unroll
        for (int mi = 0; mi < 2; mi++) {
            int m = warp_m * 32 + mi * 16 + rowin;
            ldsm4(af[mi][0], af[mi][1], af[mi][2], af[mi][3],
                  aB + (uint32_t)(m * FP + ks + kin) * 2);
        }
        #pragma unroll
        for (int np = 0; np < 4; np++) {
            int n = warp_n * 64 + np * 16 + rowin;
            ldsm4(bfr[np][0], bfr[np][1], bfr[np][2], bfr[np][3],
                  bB + (uint32_t)(n * FP + ks + kin) * 2);
        }
        #pragma unroll
        for (int mi = 0; mi < 2; mi++)
            #pragma unroll
            for (int np = 0; np < 4; np++)
                #pragma unroll
                for (int sub = 0; sub < 2; sub++)
                    mma16816(acc[mi][np * 2 + sub],
                             af[mi][0], af[mi][1], af[mi][2], af[mi][3],
                             bfr[np][sub], bfr[np][sub + 2]);
    }
}

// ---------------- fused LN1 + QKV GEMM (R11-validated) ---------------------
#define SM_QKV (3 * TILE_B)
__global__ void __launch_bounds__(256, 2) qkv_fused(
    const float* __restrict__ x, const __nv_bfloat16* __restrict__ wq,
    const float* __restrict__ ln_g, const float* __restrict__ ln_b,
    const float* __restrict__ bq, __nv_bfloat16* __restrict__ qkvb)
{
    extern __shared__ __align__(16) char smem[];
    uint32_t aB = (uint32_t)__cvta_generic_to_shared(smem);
    uint32_t wB = aB + TILE_B;
    int tid = threadIdx.x, lane = tid & 31, warp = tid >> 5;
    int warp_m = warp & 3, warp_n = warp >> 2;
    int blockM = blockIdx.x * 128;

    load_w136(wB, wq, CC, tid);                     CP_COMMIT();
    load_w136(wB + TILE_B, wq + 128 * CC, CC, tid); CP_COMMIT();
    ln_to_smem(x, aB, ln_g, ln_b, blockM, 1, tid);

    int grp   = lane >> 3;
    int rowin = (lane & 7) | ((grp & 1) << 3);
    int kin   = (grp >> 1) << 3;

    #pragma unroll
    for (int t = 0; t < 3; t++) {
        if (t < 2) asm volatile("cp.async.wait_group 1;" ::: "memory");
        else       asm volatile("cp.async.wait_group 0;" ::: "memory");
        __syncthreads();

        float acc[2][8][4];
        #pragma unroll
        for (int i = 0; i < 2; i++)
            #pragma unroll
            for (int j = 0; j < 8; j++)
                #pragma unroll
                for (int k = 0; k < 4; k++) acc[i][j][k] = 0.f;

        wtile_mma(aB, wB + (t & 1) * TILE_B, acc, warp_m, warp_n, rowin, kin);
        __syncthreads();
        if (t == 0) { load_w136(wB, wq + 256 * CC, CC, tid); CP_COMMIT(); }

        #pragma unroll
        for (int mi = 0; mi < 2; mi++)
            #pragma unroll
            for (int h2 = 0; h2 < 2; h2++) {
                int r = blockM + warp_m * 32 + mi * 16 + (lane >> 2) + h2 * 8;
                #pragma unroll
                for (int ni = 0; ni < 8; ni++) {
                    int cl = warp_n * 64 + ni * 8 + (lane & 3) * 2;
                    int c = t * 128 + cl;
                    float v0 = acc[mi][ni][h2 * 2 + 0] + bq[c];
                    float v1 = acc[mi][ni][h2 * 2 + 1] + bq[c + 1];
                    *(__nv_bfloat162*)(qkvb + (size_t)r * (3 * CC) + c) =
                        __floats2bfloat162_rn(v0, v1);
                }
            }
    }
}

// ---------------- fused MLP: LN2-input -> fc1 -> GELU -> fc2 -> +x1 --------
// 8 warps, each owns 16 rows. fc1 output repacked C->A in registers (attn
// P-trick); acc2 persists across the 4 K-chunks. No act tensor, no smem act.
#define SM_MLP2 (5 * TILE_B)    // A + 2xW1 + 2xW2 = 174080 B
__global__ void __launch_bounds__(256, 1) mlp2_fused(
    const __nv_bfloat16* __restrict__ A, const __nv_bfloat16* __restrict__ w1,
    const __nv_bfloat16* __restrict__ w2,
    const float* __restrict__ b1, const float* __restrict__ b2,
    const float* __restrict__ x1, float* __restrict__ out)
{
    extern __shared__ __align__(16) char smem[];
    uint32_t aB  = (uint32_t)__cvta_generic_to_shared(smem);
    uint32_t w1B = aB + TILE_B;
    uint32_t w2B = w1B + 2 * TILE_B;
    int tid = threadIdx.x, lane = tid & 31, warp = tid >> 5;
    int wr = warp * 16;
    int blockM = blockIdx.x * 128;

    // prologue: G0 = A + W1[0] + W2[0]; G1 = W1[1] + W2[1]
    load_w136(aB, A + (size_t)blockM * CC, CC, tid);
    load_w136(w1B, w1, CC, tid);
    load_w136(w2B, w2, MLPH, tid);                       CP_COMMIT();
    load_w136(w1B + TILE_B, w1 + 128 * CC, CC, tid);
    load_w136(w2B + TILE_B, w2 + 128, MLPH, tid);        CP_COMMIT();

    int grp   = lane >> 3;
    int rowin = (lane & 7) | ((grp & 1) << 3);
    int kin   = (grp >> 1) << 3;

    float acc2[16][4];
    #pragma unroll
    for (int i = 0; i < 16; i++)
        #pragma unroll
        for (int j = 0; j < 4; j++) acc2[i][j] = 0.f;

    #pragma unroll
    for (int t = 0; t < 4; t++) {
        if (t < 3) asm volatile("cp.async.wait_group 1;" ::: "memory");
        else       asm volatile("cp.async.wait_group 0;" ::: "memory");
        __syncthreads();

        uint32_t w1S = w1B + (t & 1) * TILE_B;
        uint32_t w2S = w2B + (t & 1) * TILE_B;

        // fc1 in two 64-col halves to cap registers; pack act into pa[8][4]
        uint32_t pa[8][4];
        #pragma unroll
        for (int h = 0; h < 2; h++) {
            float acc1[8][4];
            #pragma unroll
            for (int i = 0; i < 8; i++)
                #pragma unroll
                for (int j = 0; j < 4; j++) acc1[i][j] = 0.f;

            #pragma unroll
            for (int ks = 0; ks < 128; ks += 16) {
                uint32_t af[4];
                ldsm4(af[0], af[1], af[2], af[3],
                      aB + (uint32_t)((wr + rowin) * FP + ks + kin) * 2);
                #pragma unroll
                for (int np = 0; np < 4; np++) {
                    uint32_t bfr[4];
                    ldsm4(bfr[0], bfr[1], bfr[2], bfr[3],
                          w1S + (uint32_t)((h * 64 + np * 16 + rowin) * FP + ks + kin) * 2);
                    mma16816(acc1[np * 2 + 0], af[0], af[1], af[2], af[3], bfr[0], bfr[2]);
                    mma16816(acc1[np * 2 + 1], af[0], af[1], af[2], af[3], bfr[1], bfr[3]);
                }
            }
            // bias + GELU + pack (C-layout -> A-layout)
            #pragma unroll
            for (int j = 0; j < 4; j++) {
                int cb = t * 128 + h * 64 + j * 16 + (lane & 3) * 2;
                float2 bA = *(const float2*)(b1 + cb);
                float2 bB = *(const float2*)(b1 + cb + 8);
                float v00 = acc1[2*j][0]   + bA.x, v01 = acc1[2*j][1]   + bA.y;
                float v10 = acc1[2*j][2]   + bA.x, v11 = acc1[2*j][3]   + bA.y;
                float v20 = acc1[2*j+1][0] + bB.x, v21 = acc1[2*j+1][1] + bB.y;
                float v30 = acc1[2*j+1][2] + bB.x, v31 = acc1[2*j+1][3] + bB.y;
                v00 = 0.5f*v00*(1.f+erff(v00*0.70710678118654752f));
                v01 = 0.5f*v01*(1.f+erff(v01*0.70710678118654752f));
                v10 = 0.5f*v10*(1.f+erff(v10*0.70710678118654752f));
                v11 = 0.5f*v11*(1.f+erff(v11*0.70710678118654752f));
                v20 = 0.5f*v20*(1.f+erff(v20*0.70710678118654752f));
                v21 = 0.5f*v21*(1.f+erff(v21*0.70710678118654752f));
                v30 = 0.5f*v30*(1.f+erff(v30*0.70710678118654752f));
                v31 = 0.5f*v31*(1.f+erff(v31*0.70710678118654752f));
                pa[h*4 + j][0] = pack_bf2(v00, v01);
                pa[h*4 + j][1] = pack_bf2(v10, v11);
                pa[h*4 + j][2] = pack_bf2(v20, v21);
                pa[h*4 + j][3] = pack_bf2(v30, v31);
            }
        }

        // fc2: k-steps j over this tile's 128 k (pa[j] covers k = j*16)
        #pragma unroll
        for (int j = 0; j < 8; j++) {
            #pragma unroll
            for (int np = 0; np < 8; np++) {
                uint32_t bfr[4];
                ldsm4(bfr[0], bfr[1], bfr[2], bfr[3],
                      w2S + (uint32_t)((np * 16 + rowin) * FP + j * 16 + kin) * 2);
                mma16816(acc2[np * 2 + 0], pa[j][0], pa[j][1], pa[j][2], pa[j][3], bfr[0], bfr[2]);
                mma16816(acc2[np * 2 + 1], pa[j][0], pa[j][1], pa[j][2], pa[j][3], bfr[1], bfr[3]);
            }
        }
        __syncthreads();
        if (t + 2 < 4) {
            load_w136(w1B + (t & 1) * TILE_B, w1 + (size_t)(t + 2) * 128 * CC, CC, tid);
            load_w136(w2B + (t & 1) * TILE_B, w2 + (t + 2) * 128, MLPH, tid);
            CP_COMMIT();
        }
    }

    // epilogue: out = x1 + b2 + acc2 (fp32)
    #pragma unroll
    for (int h2 = 0; h2 < 2; h2++) {
        int r = blockM + wr + (lane >> 2) + h2 * 8;
        #pragma unroll
        for (int nt = 0; nt < 16; nt++) {
            int c = nt * 8 + (lane & 3) * 2;
            float2 e = *(const float2*)(x1 + (size_t)r * CC + c);
            float2 bi = *(const float2*)(b2 + c);
            float2 ov;
            ov.x = e.x + bi.x + acc2[nt][h2 * 2 + 0];
            ov.y = e.y + bi.y + acc2[nt][h2 * 2 + 1];
            *(float2*)(out + (size_t)r * CC + c) = ov;
        }
    }
}

// ============ 2-stage cp.async GEMM pieces (proj_ln) =======================
#define KC     32
#define SPITCH 40
#define STAGEB (128 * SPITCH * 2)

// ---------------- proj GEMM + scatter + residual + fused LN2 (R12) ---------
#define XBUF_OFF (4 * STAGEB)
#define SM_PROJLN (XBUF_OFF + 128 * 136 * 2)

__global__ void __launch_bounds__(256, 2) proj_ln(
    const __nv_bfloat16* __restrict__ A, const __nv_bfloat16* __restrict__ W,
    const float* __restrict__ bias, float* __restrict__ x1out,
    const float* __restrict__ xres,
    const float* __restrict__ ln_g, const float* __restrict__ ln_b,
    __nv_bfloat16* __restrict__ hwin)
{
    extern __shared__ __align__(16) char smem[];
    const int K = CC;
    uint32_t aBase = (uint32_t)__cvta_generic_to_shared(smem);
    uint32_t bBase = aBase + 2 * STAGEB;
    __nv_bfloat16* xbuf = (__nv_bfloat16*)(smem + XBUF_OFF);

    int tid = threadIdx.x, lane = tid & 31, warp = tid >> 5;
    int warp_m = warp & 3, warp_n = warp >> 2;
    int blockM = blockIdx.x * 128;

    float acc[2][8][4];
    #pragma unroll
    for (int i = 0; i < 2; i++)
        #pragma unroll
        for (int j = 0; j < 8; j++)
            #pragma unroll
            for (int k = 0; k < 4; k++) acc[i][j][k] = 0.f;

    int grp   = lane >> 3;
    int rowin = (lane & 7) | ((grp & 1) << 3);
    int kin   = (grp >> 1) << 3;

    int r8 = tid >> 2, k8 = (tid & 3) * 8;
    int r8b = (tid + 256) >> 2, k8b = ((tid + 256) & 3) * 8;

    cp16(aBase + (r8  * SPITCH + k8 ) * 2, A + (size_t)(blockM + r8 ) * K + k8 );
    cp16(aBase + (r8b * SPITCH + k8b) * 2, A + (size_t)(blockM + r8b) * K + k8b);
    cp16(bBase + (r8  * SPITCH + k8 ) * 2, W + (size_t)r8  * K + k8 );
    cp16(bBase + (r8b * SPITCH + k8b) * 2, W + (size_t)r8b * K + k8b);
    asm volatile("cp.async.commit_group;\n");

    int nk = K >> 5;
    for (int s = 0; s < nk; s++) {
        if (s + 1 < nk) {
            int kt = (s + 1) << 5;
            uint32_t ao = aBase + ((s + 1) & 1) * STAGEB;
            uint32_t bo = bBase + ((s + 1) & 1) * STAGEB;
            cp16(ao + (r8  * SPITCH + k8 ) * 2, A + (size_t)(blockM + r8 ) * K + kt + k8 );
            cp16(ao + (r8b * SPITCH + k8b) * 2, A + (size_t)(blockM + r8b) * K + kt + k8b);
            cp16(bo + (r8  * SPITCH + k8 ) * 2, W + (size_t)r8  * K + kt + k8 );
            cp16(bo + (r8b * SPITCH + k8b) * 2, W + (size_t)r8b * K + kt + k8b);
            asm volatile("cp.async.commit_group;\n");
            asm volatile("cp.async.wait_group 1;\n");
        } else {
            asm volatile("cp.async.wait_group 0;\n");
        }
        __syncthreads();

        uint32_t aS = aBase + (s & 1) * STAGEB;
        uint32_t bS = bBase + (s & 1) * STAGEB;
        #pragma unroll
        for (int ks = 0; ks < KC; ks += 16) {
            uint32_t af[2][4], bfr[4][4];
            #pragma unroll
            for (int mi = 0; mi < 2; mi++) {
                int m = warp_m * 32 + mi * 16 + rowin;
                ldsm4(af[mi][0], af[mi][1], af[mi][2], af[mi][3],
                      aS + (uint32_t)(m * SPITCH + ks + kin) * 2);
            }
            #pragma unroll
            for (int np = 0; np < 4; np++) {
                int n = warp_n * 64 + np * 16 + rowin;
                ldsm4(bfr[np][0], bfr[np][1], bfr[np][2], bfr[np][3],
                      bS + (uint32_t)(n * SPITCH + ks + kin) * 2);
            }
            #pragma unroll
            for (int mi = 0; mi < 2; mi++)
                #pragma unroll
                for (int np = 0; np < 4; np++)
                    #pragma unroll
                    for (int sub = 0; sub < 2; sub++)
                        mma16816(acc[mi][np * 2 + sub],
                                 af[mi][0], af[mi][1], af[mi][2], af[mi][3],
                                 bfr[np][sub], bfr[np][sub + 2]);
        }
        __syncthreads();
    }

    #pragma unroll
    for (int mi = 0; mi < 2; mi++)
        #pragma unroll
        for (int h2 = 0; h2 < 2; h2++) {
            int rl = warp_m * 32 + mi * 16 + (lane >> 2) + h2 * 8;
            size_t orow = (size_t)win_to_img(blockM + rl);
            #pragma unroll
            for (int ni = 0; ni < 8; ni++) {
                int c = warp_n * 64 + ni * 8 + (lane & 3) * 2;
                float2 bi = *(const float2*)(bias + c);
                float2 e = *(const float2*)(xres + orow * CC + c);
                float v0 = e.x + bi.x + acc[mi][ni][h2 * 2 + 0];
                float v1 = e.y + bi.y + acc[mi][ni][h2 * 2 + 1];
                x1out[orow * CC + c]     = v0;
                x1out[orow * CC + c + 1] = v1;
                *(__nv_bfloat162*)(xbuf + rl * 136 + c) = __floats2bfloat162_rn(v0, v1);
            }
        }
    __syncthreads();

    {
        float4 gg = *(const float4*)(ln_g + lane * 4);
        float4 bb = *(const float4*)(ln_b + lane * 4);
        #pragma unroll
        for (int i = 0; i < 16; i++) {
            int rl = i * 8 + warp;
            const __nv_bfloat16* row = xbuf + rl * 136 + lane * 4;
            __nv_bfloat162 q0 = *(const __nv_bfloat162*)(row);
            __nv_bfloat162 q1 = *(const __nv_bfloat162*)(row + 2);
            float vx = __bfloat162float(q0.x), vy = __bfloat162float(q0.y);
            float vz = __bfloat162float(q1.x), vw = __bfloat162float(q1.y);
            float s = vx + vy + vz + vw;
            #pragma unroll
            for (int o = 16; o; o >>= 1) s += __shfl_xor_sync(~0u, s, o);
            float mean = s * (1.f / CC);
            float dx = vx - mean, dy = vy - mean, dz = vz - mean, dw = vw - mean;
            float vv = dx*dx + dy*dy + dz*dz + dw*dw;
            #pragma unroll
            for (int o = 16; o; o >>= 1) vv += __shfl_xor_sync(~0u, vv, o);
            float rstd = rsqrtf(vv * (1.f / CC) + 1e-5f);
            size_t orow = (size_t)win_to_img(blockM + rl);
            __nv_bfloat162 p0 = __floats2bfloat162_rn(dx * rstd * gg.x + bb.x, dy * rstd * gg.y + bb.y);
            __nv_bfloat162 p1 = __floats2bfloat162_rn(dz * rstd * gg.z + bb.z, dw * rstd * gg.w + bb.w);
            *(__nv_bfloat162*)(hwin + orow * CC + lane * 4)     = p0;
            *(__nv_bfloat162*)(hwin + orow * CC + lane * 4 + 2) = p1;
        }
    }
}

// ---------------- tensor-core window attention (bm bf16, R13) --------------
__global__ void __launch_bounds__(128) attn_tc(
    const __nv_bfloat16* __restrict__ qkv, const __nv_bfloat16* __restrict__ bm,
    __nv_bfloat16* __restrict__ obuf)
{
    int w = blockIdx.x >> 2, h = blockIdx.x & 3;
    int tid = threadIdx.x, lane = tid & 31, warp = tid >> 5;

    __shared__ __align__(16) __nv_bfloat16 qs[64 * 40];
    __shared__ __align__(16) __nv_bfloat16 ks[64 * 40];
    __shared__ __align__(16) __nv_bfloat16 vsn[64 * 40];

    size_t base = (size_t)w * NTOK * (3 * CC) + h * HD;

    #pragma unroll
    for (int i = tid; i < 256; i += 128) {
        int n = i >> 2, j = i & 3;
        uint4 qv = {0,0,0,0}, kv = {0,0,0,0}, vv = {0,0,0,0};
        if (n < NTOK) {
            const __nv_bfloat16* src = qkv + base + (size_t)n * (3 * CC) + j * 8;
            qv = *(const uint4*)(src);
            kv = *(const uint4*)(src + CC);
            vv = *(const uint4*)(src + 2 * CC);
        }
        *(uint4*)&qs [n * 40 + j * 8] = qv;
        *(uint4*)&ks [n * 40 + j * 8] = kv;
        *(uint4*)&vsn[n * 40 + j * 8] = vv;
    }
    __syncthreads();

    int grp   = lane >> 3;
    int rowin = (lane & 7) | ((grp & 1) << 3);
    int kin   = (grp >> 1) << 3;
    uint32_t qB = (uint32_t)__cvta_generic_to_shared(qs);
    uint32_t kB = (uint32_t)__cvta_generic_to_shared(ks);
    uint32_t vB = (uint32_t)__cvta_generic_to_shared(vsn);

    float acc[8][4];
    #pragma unroll
    for (int i = 0; i < 8; i++)
        #pragma unroll
        for (int j = 0; j < 4; j++) acc[i][j] = 0.f;

    int r0 = warp * 16;
    #pragma unroll
    for (int kk = 0; kk < 32; kk += 16) {
        uint32_t af[4];
        ldsm4(af[0], af[1], af[2], af[3],
              qB + (uint32_t)((r0 + rowin) * 40 + kk + kin) * 2);
        #pragma unroll
        for (int np = 0; np < 4; np++) {
            uint32_t bv[4];
            ldsm4(bv[0], bv[1], bv[2], bv[3],
                  kB + (uint32_t)((np * 16 + rowin) * 40 + kk + kin) * 2);
            mma16816(acc[np * 2 + 0], af[0], af[1], af[2], af[3], bv[0], bv[2]);
            mma16816(acc[np * 2 + 1], af[0], af[1], af[2], af[3], bv[1], bv[3]);
        }
    }

    int rA = r0 + (lane >> 2);
    int widx = w & 63;
    int wt = (((widx >> 3) == 7) ? 2 : 0) | (((widx & 7) == 7) ? 1 : 0);
    const __nv_bfloat16* bmA = bm + (((wt << 2) | h) << 12) + rA * 64;
    const __nv_bfloat16* bmB = bmA + 8 * 64;
    int mcol = (lane & 3) * 2;
    #pragma unroll
    for (int nt = 0; nt < 8; nt++) {
        float2 bA = __bfloat1622float2(*(const __nv_bfloat162*)(bmA + nt * 8 + mcol));
        float2 bB = __bfloat1622float2(*(const __nv_bfloat162*)(bmB + nt * 8 + mcol));
        acc[nt][0] += bA.x; acc[nt][1] += bA.y;
        acc[nt][2] += bB.x; acc[nt][3] += bB.y;
    }

    float mA = -1e30f, mB = -1e30f;
    #pragma unroll
    for (int nt = 0; nt < 8; nt++) {
        mA = fmaxf(mA, fmaxf(acc[nt][0], acc[nt][1]));
        mB = fmaxf(mB, fmaxf(acc[nt][2], acc[nt][3]));
    }
    mA = fmaxf(mA, __shfl_xor_sync(~0u, mA, 1));
    mA = fmaxf(mA, __shfl_xor_sync(~0u, mA, 2));
    mB = fmaxf(mB, __shfl_xor_sync(~0u, mB, 1));
    mB = fmaxf(mB, __shfl_xor_sync(~0u, mB, 2));
    float sA = 0.f, sB = 0.f;
    #pragma unroll
    for (int nt = 0; nt < 8; nt++) {
        acc[nt][0] = __expf(acc[nt][0] - mA);
        acc[nt][1] = __expf(acc[nt][1] - mA);
        acc[nt][2] = __expf(acc[nt][2] - mB);
        acc[nt][3] = __expf(acc[nt][3] - mB);
        sA += acc[nt][0] + acc[nt][1];
        sB += acc[nt][2] + acc[nt][3];
    }
    sA += __shfl_xor_sync(~0u, sA, 1);
    sA += __shfl_xor_sync(~0u, sA, 2);
    sB += __shfl_xor_sync(~0u, sB, 1);
    sB += __shfl_xor_sync(~0u, sB, 2);
    float invA = 1.f / sA, invB = 1.f / sB;

    uint32_t pa[4][4];
    #pragma unroll
    for (int j = 0; j < 4; j++) {
        pa[j][0] = pack_bf2(acc[2*j][0]   * invA, acc[2*j][1]   * invA);
        pa[j][1] = pack_bf2(acc[2*j][2]   * invB, acc[2*j][3]   * invB);
        pa[j][2] = pack_bf2(acc[2*j+1][0] * invA, acc[2*j+1][1] * invA);
        pa[j][3] = pack_bf2(acc[2*j+1][2] * invB, acc[2*j+1][3] * invB);
    }

    float oacc[4][4];
    #pragma unroll
    for (int i = 0; i < 4; i++)
        #pragma unroll
        for (int j = 0; j < 4; j++) oacc[i][j] = 0.f;

    int vrow = (lane & 7) | ((grp >> 1) << 3);
    int vcol = (grp & 1) * 8;
    #pragma unroll
    for (int j = 0; j < 4; j++) {
        #pragma unroll
        for (int dg = 0; dg < 2; dg++) {
            uint32_t bv[4];
            ldsm4t(bv[0], bv[1], bv[2], bv[3],
                   vB + (uint32_t)((j * 16 + vrow) * 40 + dg * 16 + vcol) * 2);
            mma16816(oacc[dg * 2 + 0], pa[j][0], pa[j][1], pa[j][2], pa[j][3], bv[0], bv[2]);
            mma16816(oacc[dg * 2 + 1], pa[j][0], pa[j][1], pa[j][2], pa[j][3], bv[1], bv[3]);
        }
    }

    int rB = rA + 8;
    #pragma unroll
    for (int nd = 0; nd < 4; nd++) {
        int c = h * HD + nd * 8 + (lane & 3) * 2;
        if (rA < NTOK)
            *(__nv_bfloat162*)(obuf + ((size_t)w * NTOK + rA) * CC + c) =
                __floats2bfloat162_rn(oacc[nd][0], oacc[nd][1]);
        if (rB < NTOK)
            *(__nv_bfloat162*)(obuf + ((size_t)w * NTOK + rB) * CC + c) =
                __floats2bfloat162_rn(oacc[nd][2], oacc[nd][3]);
    }
}

// ---------------- launch --------------------------------------------------
extern "C" void kernel_launch(void* const* d_in, const int* in_sizes, int n_in,
                              void* d_out, int out_size)
{
    const float* x      = (const float*)d_in[0];
    const float* ln1_g  = (const float*)d_in[1];
    const float* ln1_b  = (const float*)d_in[2];
    const float* qkv_w  = (const float*)d_in[3];
    const float* qkv_b  = (const float*)d_in[4];
    const float* rpb    = (const float*)d_in[5];
    const float* proj_w = (const float*)d_in[6];
    const float* proj_b = (const float*)d_in[7];
    const float* ln2_g  = (const float*)d_in[8];
    const float* ln2_b  = (const float*)d_in[9];
    const float* fc1_w  = (const float*)d_in[10];
    const float* fc1_b  = (const float*)d_in[11];
    const float* fc2_w  = (const float*)d_in[12];
    const float* fc2_b  = (const float*)d_in[13];
    float* out = (float*)d_out;

    __nv_bfloat16 *hwin, *qkvb, *obuf, *wq, *wp, *wf1, *wf2, *bm;
    float *x1, *bq;
    cudaGetSymbolAddress((void**)&hwin, g_hwin);
    cudaGetSymbolAddress((void**)&qkvb, g_qkv);
    cudaGetSymbolAddress((void**)&obuf, g_obuf);
    cudaGetSymbolAddress((void**)&x1,   g_x1);
    cudaGetSymbolAddress((void**)&wq,   g_wq);
    cudaGetSymbolAddress((void**)&wp,   g_wp);
    cudaGetSymbolAddress((void**)&wf1,  g_wf1);
    cudaGetSymbolAddress((void**)&wf2,  g_wf2);
    cudaGetSymbolAddress((void**)&bq,   g_bq);
    cudaGetSymbolAddress((void**)&bm,   g_bm);

    static int init_done = 0;
    if (!init_done) {
        cudaFuncSetAttribute(qkv_fused, cudaFuncAttributeMaxDynamicSharedMemorySize, SM_QKV);
        cudaFuncSetAttribute(mlp2_fused, cudaFuncAttributeMaxDynamicSharedMemorySize, SM_MLP2);
        cudaFuncSetAttribute(proj_ln, cudaFuncAttributeMaxDynamicSharedMemorySize, SM_PROJLN);
        init_done = 1;
    }

    // 0) weight conversions + fused bias/mask table (one launch)
    f2bf_all<<<768, 256>>>(qkv_w, proj_w, fc1_w, fc2_w, qkv_b, rpb,
                           wq, wp, wf1, wf2, bq, bm);

    // 1) LN1 + shift/gather + QKV projection (fused)
    qkv_fused<<<MROWS / 128, 256, SM_QKV>>>(x, wq, ln1_g, ln1_b, bq, qkvb);
    // 2) tensor-core window attention
    attn_tc<<<TOTW * NH, 128>>>(qkvb, bm, obuf);
    // 3) proj + scatter + residual + fused LN2 -> x1 fp32 + hwin bf16
    proj_ln<<<MROWS / 128, 256, SM_PROJLN>>>(obuf, wp, proj_b, x1, x, ln2_g, ln2_b, hwin);
    // 4) fc1 + GELU + fc2 + residual (fully fused, no act tensor)
    mlp2_fused<<<MROWS / 128, 256, SM_MLP2>>>(hwin, wf1, wf2, fc1_b, fc2_b, x1, out);
}

// round 15
// speedup vs baseline: 1.1744x; 1.1744x over previous
#include <cuda_runtime.h>
#include <cuda_bf16.h>
#include <math.h>
#include <stdint.h>

// ---------------- problem constants ----------------
#define BATCH   64
#define HH      56
#define WW_DIM  56
#define CC      128
#define WIN     7
#define SHIFT   3
#define NH      4
#define HD      32
#define NTOK    49
#define TOTW    (BATCH*64)      // 4096 windows
#define MROWS   (TOTW*NTOK)     // 200704 token rows
#define MLPH    512

// ---------------- scratch ----------------
__device__ __nv_bfloat16 g_hwin[(size_t)MROWS*CC];
__device__ __nv_bfloat16 g_qkv [(size_t)MROWS*3*CC];
__device__ __nv_bfloat16 g_obuf[(size_t)MROWS*CC];
__device__ float         g_x1  [(size_t)MROWS*CC];
__device__ __nv_bfloat16 g_act [(size_t)MROWS*MLPH];
__device__ __nv_bfloat16 g_wq [3*CC*CC];
__device__ __nv_bfloat16 g_wp [CC*CC];
__device__ __nv_bfloat16 g_wf1[MLPH*CC];
__device__ __nv_bfloat16 g_wf2[CC*MLPH];
__device__ float g_bq[3*CC];
__device__ __nv_bfloat16 g_bm[4*4*64*64];

__device__ __forceinline__ int win_to_img(int grow) {
    int w = grow / NTOK, n = grow - w * NTOK;
    int bi = w >> 6, widx = w & 63;
    int r = ((widx >> 3) * WIN + n / WIN + SHIFT) % HH;
    int c = ((widx & 7)  * WIN + n % WIN + SHIFT) % WW_DIM;
    return bi * (HH * WW_DIM) + r * WW_DIM + c;
}

#define QSCALE 0.17677669529663687f

// ------- weights fp32 -> bf16 (+ fold q scale) + bias/mask table, 1 launch --
__global__ void f2bf_all(const float* __restrict__ w0, const float* __restrict__ w1,
                         const float* __restrict__ w2, const float* __restrict__ w3,
                         const float* __restrict__ qb, const float* __restrict__ rpb,
                         __nv_bfloat16* o0, __nv_bfloat16* o1,
                         __nv_bfloat16* o2, __nv_bfloat16* o3,
                         float* bq, __nv_bfloat16* bm)
{
    int i = blockIdx.x * 256 + threadIdx.x;
    if (i < 49152) {
        float v = w0[i];
        if (i < 16384) v *= QSCALE;
        o0[i] = __float2bfloat16_rn(v);
    }
    else if (i < 65536)  o1[i - 49152]  = __float2bfloat16_rn(w1[i - 49152]);
    else if (i < 131072) o2[i - 65536]  = __float2bfloat16_rn(w2[i - 65536]);
    else                 o3[i - 131072] = __float2bfloat16_rn(w3[i - 131072]);
    if (i < 384) bq[i] = qb[i] * (i < 128 ? QSCALE : 1.f);

    if (i < 65536) {
        int m = i & 63, n = (i >> 6) & 63, h = (i >> 12) & 3, wt = i >> 14;
        float v;
        if (m >= NTOK) v = -1e30f;
        else {
            int ne = n < NTOK ? n : NTOK - 1;
            int ny = ne / 7, nx = ne % 7, my = m / 7, mx = m % 7;
            v = rpb[((ny - my + 6) * 13 + (nx - mx + 6)) * NH + h];
            int wh7 = wt >> 1, ww7 = wt & 1;
            int lrn = wh7 ? (ny < 4 ? 1 : 2) : 0;
            int lcn = ww7 ? (nx < 4 ? 1 : 2) : 0;
            int lrm = wh7 ? (my < 4 ? 1 : 2) : 0;
            int lcm = ww7 ? (mx < 4 ? 1 : 2) : 0;
            if (lrn * 3 + lcn != lrm * 3 + lcm) v -= 100.f;
        }
        bm[i] = __float2bfloat16_rn(v);
    }
}

// ---------------- HMMA / cp.async helpers ----------------
__device__ __forceinline__ void ldsm4(uint32_t &r0, uint32_t &r1, uint32_t &r2, uint32_t &r3, uint32_t addr) {
    asm volatile("ldmatrix.sync.aligned.m8n8.x4.shared.b16 {%0,%1,%2,%3}, [%4];\n"
                 : "=r"(r0), "=r"(r1), "=r"(r2), "=r"(r3) : "r"(addr));
}
__device__ __forceinline__ void ldsm4t(uint32_t &r0, uint32_t &r1, uint32_t &r2, uint32_t &r3, uint32_t addr) {
    asm volatile("ldmatrix.sync.aligned.m8n8.x4.trans.shared.b16 {%0,%1,%2,%3}, [%4];\n"
                 : "=r"(r0), "=r"(r1), "=r"(r2), "=r"(r3) : "r"(addr));
}
__device__ __forceinline__ void mma16816(float c[4], uint32_t a0, uint32_t a1, uint32_t a2, uint32_t a3,
                                         uint32_t b0, uint32_t b1) {
    asm volatile("mma.sync.aligned.m16n8k16.row.col.f32.bf16.bf16.f32 "
                 "{%0,%1,%2,%3}, {%4,%5,%6,%7}, {%8,%9}, {%0,%1,%2,%3};\n"
                 : "+f"(c[0]), "+f"(c[1]), "+f"(c[2]), "+f"(c[3])
                 : "r"(a0), "r"(a1), "r"(a2), "r"(a3), "r"(b0), "r"(b1));
}
__device__ __forceinline__ uint32_t pack_bf2(float a, float b) {
    __nv_bfloat162 p = __floats2bfloat162_rn(a, b);
    return *(uint32_t*)&p;
}
__device__ __forceinline__ void cp16(uint32_t dst, const void* src) {
    asm volatile("cp.async.ca.shared.global [%0], [%1], 16;\n" :: "r"(dst), "l"(src));
}
#define CP_COMMIT() asm volatile("cp.async.commit_group;\n" ::: "memory")

// ============ full-K resident tiles (pitch 136) ============================
#define FP 136
#define TILE_B (128 * FP * 2)   // 34816 bytes

__device__ __forceinline__ void load_w136(uint32_t dst, const __nv_bfloat16* src,
                                          int ldk, int tid)
{
    #pragma unroll
    for (int i = 0; i < 8; i++) {
        int ch = i * 256 + tid;
        int r = ch >> 4, c8 = ch & 15;
        cp16(dst + (uint32_t)(r * FP + c8 * 8) * 2, src + (size_t)r * ldk + c8 * 8);
    }
}

// inline LayerNorm: 128 rows, warp per row, bf16 smem out
__device__ __forceinline__ void ln_to_smem(const float* __restrict__ in, uint32_t dstB,
    const float* __restrict__ g, const float* __restrict__ b,
    int blockM, int gather, int tid)
{
    int warp = tid >> 5, lane = tid & 31;
    float4 gg = *(const float4*)(g + lane * 4);
    float4 bb = *(const float4*)(b + lane * 4);
    #pragma unroll
    for (int i = 0; i < 16; i++) {
        int r = i * 8 + warp;
        int row = blockM + r;
        int src = gather ? win_to_img(row) : row;
        float4 v = *(const float4*)(in + (size_t)src * CC + lane * 4);
        float s = v.x + v.y + v.z + v.w;
        #pragma unroll
        for (int o = 16; o; o >>= 1) s += __shfl_xor_sync(~0u, s, o);
        float mean = s * (1.f / CC);
        float dx = v.x - mean, dy = v.y - mean, dz = v.z - mean, dw = v.w - mean;
        float vv = dx*dx + dy*dy + dz*dz + dw*dw;
        #pragma unroll
        for (int o = 16; o; o >>= 1) vv += __shfl_xor_sync(~0u, vv, o);
        float rstd = rsqrtf(vv * (1.f / CC) + 1e-5f);
        uint32_t p0 = pack_bf2(dx * rstd * gg.x + bb.x, dy * rstd * gg.y + bb.y);
        uint32_t p1 = pack_bf2(dz * rstd * gg.z + bb.z, dw * rstd * gg.w + bb.w);
        asm volatile("st.shared.v2.b32 [%0], {%1,%2};" ::
                     "r"(dstB + (uint32_t)(r * FP + lane * 4) * 2), "r"(p0), "r"(p1) : "memory");
    }
}

// full-K (128) warp-tile MMA on pitch-136 smem: 32x64 warp tile
__device__ __forceinline__ void wtile_mma(uint32_t aB, uint32_t bB, float acc[2][8][4],
                                          int warp_m, int warp_n, int rowin, int kin)
{
    #pragma unroll
    for (int ks = 0; ks < 128; ks += 16) {
        uint32_t af[2][4], bfr[4][4];
        #pragma unroll
        for (int mi = 0; mi < 2; mi++) {
            int m = warp_m * 32 + mi * 16 + rowin;
            ldsm4(af[mi][0], af[mi][1], af[mi][2], af[mi][3],
                  aB + (uint32_t)(m * FP + ks + kin) * 2);
        }
        #pragma unroll
        for (int np = 0; np < 4; np++) {
            int n = warp_n * 64 + np * 16 + rowin;
            ldsm4(bfr[np][0], bfr[np][1], bfr[np][2], bfr[np][3],
                  bB + (uint32_t)(n * FP + ks + kin) * 2);
        }
        #pragma unroll
        for (int mi = 0; mi < 2; mi++)
            #pragma unroll
            for (int np = 0; np < 4; np++)
                #pragma unroll
                for (int sub = 0; sub < 2; sub++)
                    mma16816(acc[mi][np * 2 + sub],
                             af[mi][0], af[mi][1], af[mi][2], af[mi][3],
                             bfr[np][sub], bfr[np][sub + 2]);
    }
}

// ---------------- fused LN1 + QKV GEMM (R11-validated) ---------------------
#define SM_QKV (3 * TILE_B)
__global__ void __launch_bounds__(256, 2) qkv_fused(
    const float* __restrict__ x, const __nv_bfloat16* __restrict__ wq,
    const float* __restrict__ ln_g, const float* __restrict__ ln_b,
    const float* __restrict__ bq, __nv_bfloat16* __restrict__ qkvb)
{
    extern __shared__ __align__(16) char smem[];
    uint32_t aB = (uint32_t)__cvta_generic_to_shared(smem);
    uint32_t wB = aB + TILE_B;
    int tid = threadIdx.x, lane = tid & 31, warp = tid >> 5;
    int warp_m = warp & 3, warp_n = warp >> 2;
    int blockM = blockIdx.x * 128;

    load_w136(wB, wq, CC, tid);                     CP_COMMIT();
    load_w136(wB + TILE_B, wq + 128 * CC, CC, tid); CP_COMMIT();
    ln_to_smem(x, aB, ln_g, ln_b, blockM, 1, tid);

    int grp   = lane >> 3;
    int rowin = (lane & 7) | ((grp & 1) << 3);
    int kin   = (grp >> 1) << 3;

    #pragma unroll
    for (int t = 0; t < 3; t++) {
        if (t < 2) asm volatile("cp.async.wait_group 1;" ::: "memory");
        else       asm volatile("cp.async.wait_group 0;" ::: "memory");
        __syncthreads();

        float acc[2][8][4];
        #pragma unroll
        for (int i = 0; i < 2; i++)
            #pragma unroll
            for (int j = 0; j < 8; j++)
                #pragma unroll
                for (int k = 0; k < 4; k++) acc[i][j][k] = 0.f;

        wtile_mma(aB, wB + (t & 1) * TILE_B, acc, warp_m, warp_n, rowin, kin);
        __syncthreads();
        if (t == 0) { load_w136(wB, wq + 256 * CC, CC, tid); CP_COMMIT(); }

        #pragma unroll
        for (int mi = 0; mi < 2; mi++)
            #pragma unroll
            for (int h2 = 0; h2 < 2; h2++) {
                int r = blockM + warp_m * 32 + mi * 16 + (lane >> 2) + h2 * 8;
                #pragma unroll
                for (int ni = 0; ni < 8; ni++) {
                    int cl = warp_n * 64 + ni * 8 + (lane & 3) * 2;
                    int c = t * 128 + cl;
                    float v0 = acc[mi][ni][h2 * 2 + 0] + bq[c];
                    float v1 = acc[mi][ni][h2 * 2 + 1] + bq[c + 1];
                    *(__nv_bfloat162*)(qkvb + (size_t)r * (3 * CC) + c) =
                        __floats2bfloat162_rn(v0, v1);
                }
            }
    }
}

// ---------------- fc1: A-resident, 4 in-CTA N-tiles, GELU epilogue ---------
// grid order REVERSED: reads hwin tail-first (L2-hot from proj_ln), and
// finishes writing act at LOW M so fc2 (normal order) hits the act head in L2
#define SM_FC1 (3 * TILE_B)
__global__ void __launch_bounds__(256, 2) fc1_fused(
    const __nv_bfloat16* __restrict__ A, const __nv_bfloat16* __restrict__ w1,
    const float* __restrict__ b1, __nv_bfloat16* __restrict__ act)
{
    extern __shared__ __align__(16) char smem[];
    uint32_t aB = (uint32_t)__cvta_generic_to_shared(smem);
    uint32_t wB = aB + TILE_B;
    int tid = threadIdx.x, lane = tid & 31, warp = tid >> 5;
    int warp_m = warp & 3, warp_n = warp >> 2;
    int blockM = (gridDim.x - 1 - blockIdx.x) * 128;   // reversed

    load_w136(aB, A + (size_t)blockM * CC, CC, tid);
    load_w136(wB, w1, CC, tid);                     CP_COMMIT();
    load_w136(wB + TILE_B, w1 + 128 * CC, CC, tid); CP_COMMIT();

    int grp   = lane >> 3;
    int rowin = (lane & 7) | ((grp & 1) << 3);
    int kin   = (grp >> 1) << 3;

    #pragma unroll
    for (int t = 0; t < 4; t++) {
        if (t < 3) asm volatile("cp.async.wait_group 1;" ::: "memory");
        else       asm volatile("cp.async.wait_group 0;" ::: "memory");
        __syncthreads();

        float acc[2][8][4];
        #pragma unroll
        for (int i = 0; i < 2; i++)
            #pragma unroll
            for (int j = 0; j < 8; j++)
                #pragma unroll
                for (int k = 0; k < 4; k++) acc[i][j][k] = 0.f;

        wtile_mma(aB, wB + (t & 1) * TILE_B, acc, warp_m, warp_n, rowin, kin);
        __syncthreads();
        if (t + 2 < 4) {
            load_w136(wB + (t & 1) * TILE_B, w1 + (size_t)(t + 2) * 128 * CC, CC, tid);
            CP_COMMIT();
        }

        #pragma unroll
        for (int mi = 0; mi < 2; mi++)
            #pragma unroll
            for (int h2 = 0; h2 < 2; h2++) {
                int r = blockM + warp_m * 32 + mi * 16 + (lane >> 2) + h2 * 8;
                #pragma unroll
                for (int ni = 0; ni < 8; ni++) {
                    int cl = warp_n * 64 + ni * 8 + (lane & 3) * 2;
                    int c = t * 128 + cl;
                    float v0 = acc[mi][ni][h2 * 2 + 0] + b1[c];
                    float v1 = acc[mi][ni][h2 * 2 + 1] + b1[c + 1];
                    v0 = 0.5f * v0 * (1.f + erff(v0 * 0.70710678118654752f));
                    v1 = 0.5f * v1 * (1.f + erff(v1 * 0.70710678118654752f));
                    *(__nv_bfloat162*)(act + (size_t)r * MLPH + c) =
                        __floats2bfloat162_rn(v0, v1);
                }
            }
    }
}

// ============ 2-stage cp.async GEMM (fc2 only; normal M order) =============
#define KC     32
#define SPITCH 40
#define STAGEB (128 * SPITCH * 2)

template<int EPI>
__global__ void __launch_bounds__(256) hgemm(
    const __nv_bfloat16* __restrict__ A, const __nv_bfloat16* __restrict__ W,
    const float* __restrict__ bias, void* __restrict__ outp,
    const float* __restrict__ extra, int M, int N, int K)
{
    __shared__ __align__(16) __nv_bfloat16 As[2][128 * SPITCH];
    __shared__ __align__(16) __nv_bfloat16 Bs[2][128 * SPITCH];

    int tid = threadIdx.x, lane = tid & 31, warp = tid >> 5;
    int warp_m = warp & 3, warp_n = warp >> 2;
    int blockM = blockIdx.x * 128, blockN = blockIdx.y * 128;

    float acc[2][8][4];
    #pragma unroll
    for (int i = 0; i < 2; i++)
        #pragma unroll
        for (int j = 0; j < 8; j++)
            #pragma unroll
            for (int k = 0; k < 4; k++) acc[i][j][k] = 0.f;

    int grp   = lane >> 3;
    int rowin = (lane & 7) | ((grp & 1) << 3);
    int kin   = (grp >> 1) << 3;

    uint32_t aBase = (uint32_t)__cvta_generic_to_shared(&As[0][0]);
    uint32_t bBase = (uint32_t)__cvta_generic_to_shared(&Bs[0][0]);

    int r8 = tid >> 2, k8 = (tid & 3) * 8;
    int r8b = (tid + 256) >> 2, k8b = ((tid + 256) & 3) * 8;

    {
        cp16(aBase + (r8  * SPITCH + k8 ) * 2, A + (size_t)(blockM + r8 ) * K + k8 );
        cp16(aBase + (r8b * SPITCH + k8b) * 2, A + (size_t)(blockM + r8b) * K + k8b);
        cp16(bBase + (r8  * SPITCH + k8 ) * 2, W + (size_t)(blockN + r8 ) * K + k8 );
        cp16(bBase + (r8b * SPITCH + k8b) * 2, W + (size_t)(blockN + r8b) * K + k8b);
        asm volatile("cp.async.commit_group;\n");
    }

    int nk = K >> 5;
    for (int s = 0; s < nk; s++) {
        if (s + 1 < nk) {
            int kt = (s + 1) << 5;
            uint32_t ao = aBase + ((s + 1) & 1) * STAGEB;
            uint32_t bo = bBase + ((s + 1) & 1) * STAGEB;
            cp16(ao + (r8  * SPITCH + k8 ) * 2, A + (size_t)(blockM + r8 ) * K + kt + k8 );
            cp16(ao + (r8b * SPITCH + k8b) * 2, A + (size_t)(blockM + r8b) * K + kt + k8b);
            cp16(bo + (r8  * SPITCH + k8 ) * 2, W + (size_t)(blockN + r8 ) * K + kt + k8 );
            cp16(bo + (r8b * SPITCH + k8b) * 2, W + (size_t)(blockN + r8b) * K + kt + k8b);
            asm volatile("cp.async.commit_group;\n");
            asm volatile("cp.async.wait_group 1;\n");
        } else {
            asm volatile("cp.async.wait_group 0;\n");
        }
        __syncthreads();

        uint32_t aS = aBase + (s & 1) * STAGEB;
        uint32_t bS = bBase + (s & 1) * STAGEB;
        #pragma unroll
        for (int ks = 0; ks < KC; ks += 16) {
            uint32_t af[2][4], bfr[4][4];
            #pragma unroll
            for (int mi = 0; mi < 2; mi++) {
                int m = warp_m * 32 + mi * 16 + rowin;
                ldsm4(af[mi][0], af[mi][1], af[mi][2], af[mi][3],
                      aS + (uint32_t)(m * SPITCH + ks + kin) * 2);
            }
            #pragma unroll
            for (int np = 0; np < 4; np++) {
                int n = warp_n * 64 + np * 16 + rowin;
                ldsm4(bfr[np][0], bfr[np][1], bfr[np][2], bfr[np][3],
                      bS + (uint32_t)(n * SPITCH + ks + kin) * 2);
            }
            #pragma unroll
            for (int mi = 0; mi < 2; mi++)
                #pragma unroll
                for (int np = 0; np < 4; np++)
                    #pragma unroll
                    for (int sub = 0; sub < 2; sub++)
                        mma16816(acc[mi][np * 2 + sub],
                                 af[mi][0], af[mi][1], af[mi][2], af[mi][3],
                                 bfr[np][sub], bfr[np][sub + 2]);
        }
        __syncthreads();
    }

    int rowBase = blockM + warp_m * 32;
    int colBase = blockN + warp_n * 64;
    #pragma unroll
    for (int mi = 0; mi < 2; mi++) {
        #pragma unroll
        for (int h2 = 0; h2 < 2; h2++) {
            int r = rowBase + mi * 16 + (lane >> 2) + h2 * 8;
            #pragma unroll
            for (int ni = 0; ni < 8; ni++) {
                int c = colBase + ni * 8 + (lane & 3) * 2;
                float v0 = acc[mi][ni][h2 * 2 + 0] + bias[c];
                float v1 = acc[mi][ni][h2 * 2 + 1] + bias[c + 1];
                float* o = (float*)outp;
                float2 e = *(const float2*)(extra + (size_t)r * N + c);
                o[(size_t)r * N + c]     = e.x + v0;
                o[(size_t)r * N + c + 1] = e.y + v1;
            }
        }
    }
}

// ---------------- proj GEMM + scatter + residual + fused LN2 (R12) ---------
#define XBUF_OFF (4 * STAGEB)
#define SM_PROJLN (XBUF_OFF + 128 * 136 * 2)

__global__ void __launch_bounds__(256, 2) proj_ln(
    const __nv_bfloat16* __restrict__ A, const __nv_bfloat16* __restrict__ W,
    const float* __restrict__ bias, float* __restrict__ x1out,
    const float* __restrict__ xres,
    const float* __restrict__ ln_g, const float* __restrict__ ln_b,
    __nv_bfloat16* __restrict__ hwin)
{
    extern __shared__ __align__(16) char smem[];
    const int K = CC;
    uint32_t aBase = (uint32_t)__cvta_generic_to_shared(smem);
    uint32_t bBase = aBase + 2 * STAGEB;
    __nv_bfloat16* xbuf = (__nv_bfloat16*)(smem + XBUF_OFF);

    int tid = threadIdx.x, lane = tid & 31, warp = tid >> 5;
    int warp_m = warp & 3, warp_n = warp >> 2;
    int blockM = blockIdx.x * 128;

    float acc[2][8][4];
    #pragma unroll
    for (int i = 0; i < 2; i++)
        #pragma unroll
        for (int j = 0; j < 8; j++)
            #pragma unroll
            for (int k = 0; k < 4; k++) acc[i][j][k] = 0.f;

    int grp   = lane >> 3;
    int rowin = (lane & 7) | ((grp & 1) << 3);
    int kin   = (grp >> 1) << 3;

    int r8 = tid >> 2, k8 = (tid & 3) * 8;
    int r8b = (tid + 256) >> 2, k8b = ((tid + 256) & 3) * 8;

    cp16(aBase + (r8  * SPITCH + k8 ) * 2, A + (size_t)(blockM + r8 ) * K + k8 );
    cp16(aBase + (r8b * SPITCH + k8b) * 2, A + (size_t)(blockM + r8b) * K + k8b);
    cp16(bBase + (r8  * SPITCH + k8 ) * 2, W + (size_t)r8  * K + k8 );
    cp16(bBase + (r8b * SPITCH + k8b) * 2, W + (size_t)r8b * K + k8b);
    asm volatile("cp.async.commit_group;\n");

    int nk = K >> 5;
    for (int s = 0; s < nk; s++) {
        if (s + 1 < nk) {
            int kt = (s + 1) << 5;
            uint32_t ao = aBase + ((s + 1) & 1) * STAGEB;
            uint32_t bo = bBase + ((s + 1) & 1) * STAGEB;
            cp16(ao + (r8  * SPITCH + k8 ) * 2, A + (size_t)(blockM + r8 ) * K + kt + k8 );
            cp16(ao + (r8b * SPITCH + k8b) * 2, A + (size_t)(blockM + r8b) * K + kt + k8b);
            cp16(bo + (r8  * SPITCH + k8 ) * 2, W + (size_t)r8  * K + kt + k8 );
            cp16(bo + (r8b * SPITCH + k8b) * 2, W + (size_t)r8b * K + kt + k8b);
            asm volatile("cp.async.commit_group;\n");
            asm volatile("cp.async.wait_group 1;\n");
        } else {
            asm volatile("cp.async.wait_group 0;\n");
        }
        __syncthreads();

        uint32_t aS = aBase + (s & 1) * STAGEB;
        uint32_t bS = bBase + (s & 1) * STAGEB;
        #pragma unroll
        for (int ks = 0; ks < KC; ks += 16) {
            uint32_t af[2][4], bfr[4][4];
            #pragma unroll
            for (int mi = 0; mi < 2; mi++) {
                int m = warp_m * 32 + mi * 16 + rowin;
                ldsm4(af[mi][0], af[mi][1], af[mi][2], af[mi][3],
                      aS + (uint32_t)(m * SPITCH + ks + kin) * 2);
            }
            #pragma unroll
            for (int np = 0; np < 4; np++) {
                int n = warp_n * 64 + np * 16 + rowin;
                ldsm4(bfr[np][0], bfr[np][1], bfr[np][2], bfr[np][3],
                      bS + (uint32_t)(n * SPITCH + ks + kin) * 2);
            }
            #pragma unroll
            for (int mi = 0; mi < 2; mi++)
                #pragma unroll
                for (int np = 0; np < 4; np++)
                    #pragma unroll
                    for (int sub = 0; sub < 2; sub++)
                        mma16816(acc[mi][np * 2 + sub],
                                 af[mi][0], af[mi][1], af[mi][2], af[mi][3],
                                 bfr[np][sub], bfr[np][sub + 2]);
        }
        __syncthreads();
    }

    #pragma unroll
    for (int mi = 0; mi < 2; mi++)
        #pragma unroll
        for (int h2 = 0; h2 < 2; h2++) {
            int rl = warp_m * 32 + mi * 16 + (lane >> 2) + h2 * 8;
            size_t orow = (size_t)win_to_img(blockM + rl);
            #pragma unroll
            for (int ni = 0; ni < 8; ni++) {
                int c = warp_n * 64 + ni * 8 + (lane & 3) * 2;
                float2 bi = *(const float2*)(bias + c);
                float2 e = *(const float2*)(xres + orow * CC + c);
                float v0 = e.x + bi.x + acc[mi][ni][h2 * 2 + 0];
                float v1 = e.y + bi.y + acc[mi][ni][h2 * 2 + 1];
                x1out[orow * CC + c]     = v0;
                x1out[orow * CC + c + 1] = v1;
                *(__nv_bfloat162*)(xbuf + rl * 136 + c) = __floats2bfloat162_rn(v0, v1);
            }
        }
    __syncthreads();

    {
        float4 gg = *(const float4*)(ln_g + lane * 4);
        float4 bb = *(const float4*)(ln_b + lane * 4);
        #pragma unroll
        for (int i = 0; i < 16; i++) {
            int rl = i * 8 + warp;
            const __nv_bfloat16* row = xbuf + rl * 136 + lane * 4;
            __nv_bfloat162 q0 = *(const __nv_bfloat162*)(row);
            __nv_bfloat162 q1 = *(const __nv_bfloat162*)(row + 2);
            float vx = __bfloat162float(q0.x), vy = __bfloat162float(q0.y);
            float vz = __bfloat162float(q1.x), vw = __bfloat162float(q1.y);
            float s = vx + vy + vz + vw;
            #pragma unroll
            for (int o = 16; o; o >>= 1) s += __shfl_xor_sync(~0u, s, o);
            float mean = s * (1.f / CC);
            float dx = vx - mean, dy = vy - mean, dz = vz - mean, dw = vw - mean;
            float vv = dx*dx + dy*dy + dz*dz + dw*dw;
            #pragma unroll
            for (int o = 16; o; o >>= 1) vv += __shfl_xor_sync(~0u, vv, o);
            float rstd = rsqrtf(vv * (1.f / CC) + 1e-5f);
            size_t orow = (size_t)win_to_img(blockM + rl);
            __nv_bfloat162 p0 = __floats2bfloat162_rn(dx * rstd * gg.x + bb.x, dy * rstd * gg.y + bb.y);
            __nv_bfloat162 p1 = __floats2bfloat162_rn(dz * rstd * gg.z + bb.z, dw * rstd * gg.w + bb.w);
            *(__nv_bfloat162*)(hwin + orow * CC + lane * 4)     = p0;
            *(__nv_bfloat162*)(hwin + orow * CC + lane * 4 + 2) = p1;
        }
    }
}

// ---------------- tensor-core window attention (bm bf16, REVERSED order) ---
__global__ void __launch_bounds__(128) attn_tc(
    const __nv_bfloat16* __restrict__ qkv, const __nv_bfloat16* __restrict__ bm,
    __nv_bfloat16* __restrict__ obuf)
{
    int w = (TOTW - 1) - (blockIdx.x >> 2);   // reversed: qkvb tail is L2-hot
    int h = blockIdx.x & 3;
    int tid = threadIdx.x, lane = tid & 31, warp = tid >> 5;

    __shared__ __align__(16) __nv_bfloat16 qs[64 * 40];
    __shared__ __align__(16) __nv_bfloat16 ks[64 * 40];
    __shared__ __align__(16) __nv_bfloat16 vsn[64 * 40];

    size_t base = (size_t)w * NTOK * (3 * CC) + h * HD;

    #pragma unroll
    for (int i = tid; i < 256; i += 128) {
        int n = i >> 2, j = i & 3;
        uint4 qv = {0,0,0,0}, kv = {0,0,0,0}, vv = {0,0,0,0};
        if (n < NTOK) {
            const __nv_bfloat16* src = qkv + base + (size_t)n * (3 * CC) + j * 8;
            qv = *(const uint4*)(src);
            kv = *(const uint4*)(src + CC);
            vv = *(const uint4*)(src + 2 * CC);
        }
        *(uint4*)&qs [n * 40 + j * 8] = qv;
        *(uint4*)&ks [n * 40 + j * 8] = kv;
        *(uint4*)&vsn[n * 40 + j * 8] = vv;
    }
    __syncthreads();

    int grp   = lane >> 3;
    int rowin = (lane & 7) | ((grp & 1) << 3);
    int kin   = (grp >> 1) << 3;
    uint32_t qB = (uint32_t)__cvta_generic_to_shared(qs);
    uint32_t kB = (uint32_t)__cvta_generic_to_shared(ks);
    uint32_t vB = (uint32_t)__cvta_generic_to_shared(vsn);

    float acc[8][4];
    #pragma unroll
    for (int i = 0; i < 8; i++)
        #pragma unroll
        for (int j = 0; j < 4; j++) acc[i][j] = 0.f;

    int r0 = warp * 16;
    #pragma unroll
    for (int kk = 0; kk < 32; kk += 16) {
        uint32_t af[4];
        ldsm4(af[0], af[1], af[2], af[3],
              qB + (uint32_t)((r0 + rowin) * 40 + kk + kin) * 2);
        #pragma unroll
        for (int np = 0; np < 4; np++) {
            uint32_t bv[4];
            ldsm4(bv[0], bv[1], bv[2], bv[3],
                  kB + (uint32_t)((np * 16 + rowin) * 40 + kk + kin) * 2);
            mma16816(acc[np * 2 + 0], af[0], af[1], af[2], af[3], bv[0], bv[2]);
            mma16816(acc[np * 2 + 1], af[0], af[1], af[2], af[3], bv[1], bv[3]);
        }
    }

    int rA = r0 + (lane >> 2);
    int widx = w & 63;
    int wt = (((widx >> 3) == 7) ? 2 : 0) | (((widx & 7) == 7) ? 1 : 0);
    const __nv_bfloat16* bmA = bm + (((wt << 2) | h) << 12) + rA * 64;
    const __nv_bfloat16* bmB = bmA + 8 * 64;
    int mcol = (lane & 3) * 2;
    #pragma unroll
    for (int nt = 0; nt < 8; nt++) {
        float2 bA = __bfloat1622float2(*(const __nv_bfloat162*)(bmA + nt * 8 + mcol));
        float2 bB = __bfloat1622float2(*(const __nv_bfloat162*)(bmB + nt * 8 + mcol));
        acc[nt][0] += bA.x; acc[nt][1] += bA.y;
        acc[nt][2] += bB.x; acc[nt][3] += bB.y;
    }

    float mA = -1e30f, mB = -1e30f;
    #pragma unroll
    for (int nt = 0; nt < 8; nt++) {
        mA = fmaxf(mA, fmaxf(acc[nt][0], acc[nt][1]));
        mB = fmaxf(mB, fmaxf(acc[nt][2], acc[nt][3]));
    }
    mA = fmaxf(mA, __shfl_xor_sync(~0u, mA, 1));
    mA = fmaxf(mA, __shfl_xor_sync(~0u, mA, 2));
    mB = fmaxf(mB, __shfl_xor_sync(~0u, mB, 1));
    mB = fmaxf(mB, __shfl_xor_sync(~0u, mB, 2));
    float sA = 0.f, sB = 0.f;
    #pragma unroll
    for (int nt = 0; nt < 8; nt++) {
        acc[nt][0] = __expf(acc[nt][0] - mA);
        acc[nt][1] = __expf(acc[nt][1] - mA);
        acc[nt][2] = __expf(acc[nt][2] - mB);
        acc[nt][3] = __expf(acc[nt][3] - mB);
        sA += acc[nt][0] + acc[nt][1];
        sB += acc[nt][2] + acc[nt][3];
    }
    sA += __shfl_xor_sync(~0u, sA, 1);
    sA += __shfl_xor_sync(~0u, sA, 2);
    sB += __shfl_xor_sync(~0u, sB, 1);
    sB += __shfl_xor_sync(~0u, sB, 2);
    float invA = 1.f / sA, invB = 1.f / sB;

    uint32_t pa[4][4];
    #pragma unroll
    for (int j = 0; j < 4; j++) {
        pa[j][0] = pack_bf2(acc[2*j][0]   * invA, acc[2*j][1]   * invA);
        pa[j][1] = pack_bf2(acc[2*j][2]   * invB, acc[2*j][3]   * invB);
        pa[j][2] = pack_bf2(acc[2*j+1][0] * invA, acc[2*j+1][1] * invA);
        pa[j][3] = pack_bf2(acc[2*j+1][2] * invB, acc[2*j+1][3] * invB);
    }

    float oacc[4][4];
    #pragma unroll
    for (int i = 0; i < 4; i++)
        #pragma unroll
        for (int j = 0; j < 4; j++) oacc[i][j] = 0.f;

    int vrow = (lane & 7) | ((grp >> 1) << 3);
    int vcol = (grp & 1) * 8;
    #pragma unroll
    for (int j = 0; j < 4; j++) {
        #pragma unroll
        for (int dg = 0; dg < 2; dg++) {
            uint32_t bv[4];
            ldsm4t(bv[0], bv[1], bv[2], bv[3],
                   vB + (uint32_t)((j * 16 + vrow) * 40 + dg * 16 + vcol) * 2);
            mma16816(oacc[dg * 2 + 0], pa[j][0], pa[j][1], pa[j][2], pa[j][3], bv[0], bv[2]);
            mma16816(oacc[dg * 2 + 1], pa[j][0], pa[j][1], pa[j][2], pa[j][3], bv[1], bv[3]);
        }
    }

    int rB = rA + 8;
    #pragma unroll
    for (int nd = 0; nd < 4; nd++) {
        int c = h * HD + nd * 8 + (lane & 3) * 2;
        if (rA < NTOK)
            *(__nv_bfloat162*)(obuf + ((size_t)w * NTOK + rA) * CC + c) =
                __floats2bfloat162_rn(oacc[nd][0], oacc[nd][1]);
        if (rB < NTOK)
            *(__nv_bfloat162*)(obuf + ((size_t)w * NTOK + rB) * CC + c) =
                __floats2bfloat162_rn(oacc[nd][2], oacc[nd][3]);
    }
}

// ---------------- launch --------------------------------------------------
extern "C" void kernel_launch(void* const* d_in, const int* in_sizes, int n_in,
                              void* d_out, int out_size)
{
    const float* x      = (const float*)d_in[0];
    const float* ln1_g  = (const float*)d_in[1];
    const float* ln1_b  = (const float*)d_in[2];
    const float* qkv_w  = (const float*)d_in[3];
    const float* qkv_b  = (const float*)d_in[4];
    const float* rpb    = (const float*)d_in[5];
    const float* proj_w = (const float*)d_in[6];
    const float* proj_b = (const float*)d_in[7];
    const float* ln2_g  = (const float*)d_in[8];
    const float* ln2_b  = (const float*)d_in[9];
    const float* fc1_w  = (const float*)d_in[10];
    const float* fc1_b  = (const float*)d_in[11];
    const float* fc2_w  = (const float*)d_in[12];
    const float* fc2_b  = (const float*)d_in[13];
    float* out = (float*)d_out;

    __nv_bfloat16 *hwin, *qkvb, *obuf, *act, *wq, *wp, *wf1, *wf2, *bm;
    float *x1, *bq;
    cudaGetSymbolAddress((void**)&hwin, g_hwin);
    cudaGetSymbolAddress((void**)&qkvb, g_qkv);
    cudaGetSymbolAddress((void**)&obuf, g_obuf);
    cudaGetSymbolAddress((void**)&x1,   g_x1);
    cudaGetSymbolAddress((void**)&act,  g_act);
    cudaGetSymbolAddress((void**)&wq,   g_wq);
    cudaGetSymbolAddress((void**)&wp,   g_wp);
    cudaGetSymbolAddress((void**)&wf1,  g_wf1);
    cudaGetSymbolAddress((void**)&wf2,  g_wf2);
    cudaGetSymbolAddress((void**)&bq,   g_bq);
    cudaGetSymbolAddress((void**)&bm,   g_bm);

    static int init_done = 0;
    if (!init_done) {
        cudaFuncSetAttribute(qkv_fused, cudaFuncAttributeMaxDynamicSharedMemorySize, SM_QKV);
        cudaFuncSetAttribute(fc1_fused, cudaFuncAttributeMaxDynamicSharedMemorySize, SM_FC1);
        cudaFuncSetAttribute(proj_ln, cudaFuncAttributeMaxDynamicSharedMemorySize, SM_PROJLN);
        init_done = 1;
    }

    // 0) weight conversions + fused bias/mask table (one launch)
    f2bf_all<<<768, 256>>>(qkv_w, proj_w, fc1_w, fc2_w, qkv_b, rpb,
                           wq, wp, wf1, wf2, bq, bm);

    // 1) LN1 + shift/gather + QKV projection (fused)
    qkv_fused<<<MROWS / 128, 256, SM_QKV>>>(x, wq, ln1_g, ln1_b, bq, qkvb);
    // 2) tensor-core window attention (reversed order: qkvb tail L2-hot)
    attn_tc<<<TOTW * NH, 128>>>(qkvb, bm, obuf);
    // 3) proj + scatter + residual + fused LN2 -> x1 fp32 + hwin bf16
    proj_ln<<<MROWS / 128, 256, SM_PROJLN>>>(obuf, wp, proj_b, x1, x, ln2_g, ln2_b, hwin);
    // 4) fc1 + GELU (reversed order: act head ends L2-hot for fc2)
    fc1_fused<<<MROWS / 128, 256, SM_FC1>>>(hwin, wf1, fc1_b, act);
    // 5) fc2 + residual -> final fp32 (normal order)
    hgemm<3><<<dim3(MROWS / 128, 1), 256>>>(act, wf2, fc2_b, out, x1, MROWS, CC, MLPH);
}

// round 16
// speedup vs baseline: 1.1995x; 1.0214x over previous
#include <cuda_runtime.h>
#include <cuda_bf16.h>
#include <math.h>
#include <stdint.h>

// ---------------- problem constants ----------------
#define BATCH   64
#define HH      56
#define WW_DIM  56
#define CC      128
#define WIN     7
#define SHIFT   3
#define NH      4
#define HD      32
#define NTOK    49
#define TOTW    (BATCH*64)      // 4096 windows
#define MROWS   (TOTW*NTOK)     // 200704 token rows
#define MLPH    512

// ---------------- scratch ----------------
__device__ __nv_bfloat16 g_hwin[(size_t)MROWS*CC];
__device__ __nv_bfloat16 g_qkv [(size_t)MROWS*3*CC];
__device__ __nv_bfloat16 g_obuf[(size_t)MROWS*CC];
__device__ float         g_x1  [(size_t)MROWS*CC];
__device__ __nv_bfloat16 g_act [(size_t)MROWS*MLPH];
__device__ __nv_bfloat16 g_wq [3*CC*CC];
__device__ __nv_bfloat16 g_wp [CC*CC];
__device__ __nv_bfloat16 g_wf1[MLPH*CC];
__device__ __nv_bfloat16 g_wf2[CC*MLPH];
__device__ float g_bq[3*CC];
__device__ __nv_bfloat16 g_bm[4*4*64*64];

__device__ __forceinline__ int win_to_img(int grow) {
    int w = grow / NTOK, n = grow - w * NTOK;
    int bi = w >> 6, widx = w & 63;
    int r = ((widx >> 3) * WIN + n / WIN + SHIFT) % HH;
    int c = ((widx & 7)  * WIN + n % WIN + SHIFT) % WW_DIM;
    return bi * (HH * WW_DIM) + r * WW_DIM + c;
}

#define QSCALE 0.17677669529663687f

// ------- weights fp32 -> bf16 (+ fold q scale) + bias/mask table, 1 launch --
__global__ void f2bf_all(const float* __restrict__ w0, const float* __restrict__ w1,
                         const float* __restrict__ w2, const float* __restrict__ w3,
                         const float* __restrict__ qb, const float* __restrict__ rpb,
                         __nv_bfloat16* o0, __nv_bfloat16* o1,
                         __nv_bfloat16* o2, __nv_bfloat16* o3,
                         float* bq, __nv_bfloat16* bm)
{
    int i = blockIdx.x * 256 + threadIdx.x;
    if (i < 49152) {
        float v = w0[i];
        if (i < 16384) v *= QSCALE;
        o0[i] = __float2bfloat16_rn(v);
    }
    else if (i < 65536)  o1[i - 49152]  = __float2bfloat16_rn(w1[i - 49152]);
    else if (i < 131072) o2[i - 65536]  = __float2bfloat16_rn(w2[i - 65536]);
    else                 o3[i - 131072] = __float2bfloat16_rn(w3[i - 131072]);
    if (i < 384) bq[i] = qb[i] * (i < 128 ? QSCALE : 1.f);

    if (i < 65536) {
        int m = i & 63, n = (i >> 6) & 63, h = (i >> 12) & 3, wt = i >> 14;
        float v;
        if (m >= NTOK) v = -1e30f;
        else {
            int ne = n < NTOK ? n : NTOK - 1;
            int ny = ne / 7, nx = ne % 7, my = m / 7, mx = m % 7;
            v = rpb[((ny - my + 6) * 13 + (nx - mx + 6)) * NH + h];
            int wh7 = wt >> 1, ww7 = wt & 1;
            int lrn = wh7 ? (ny < 4 ? 1 : 2) : 0;
            int lcn = ww7 ? (nx < 4 ? 1 : 2) : 0;
            int lrm = wh7 ? (my < 4 ? 1 : 2) : 0;
            int lcm = ww7 ? (mx < 4 ? 1 : 2) : 0;
            if (lrn * 3 + lcn != lrm * 3 + lcm) v -= 100.f;
        }
        bm[i] = __float2bfloat16_rn(v);
    }
}

// ---------------- HMMA / cp.async helpers ----------------
__device__ __forceinline__ void ldsm4(uint32_t &r0, uint32_t &r1, uint32_t &r2, uint32_t &r3, uint32_t addr) {
    asm volatile("ldmatrix.sync.aligned.m8n8.x4.shared.b16 {%0,%1,%2,%3}, [%4];\n"
                 : "=r"(r0), "=r"(r1), "=r"(r2), "=r"(r3) : "r"(addr));
}
__device__ __forceinline__ void ldsm4t(uint32_t &r0, uint32_t &r1, uint32_t &r2, uint32_t &r3, uint32_t addr) {
    asm volatile("ldmatrix.sync.aligned.m8n8.x4.trans.shared.b16 {%0,%1,%2,%3}, [%4];\n"
                 : "=r"(r0), "=r"(r1), "=r"(r2), "=r"(r3) : "r"(addr));
}
__device__ __forceinline__ void mma16816(float c[4], uint32_t a0, uint32_t a1, uint32_t a2, uint32_t a3,
                                         uint32_t b0, uint32_t b1) {
    asm volatile("mma.sync.aligned.m16n8k16.row.col.f32.bf16.bf16.f32 "
                 "{%0,%1,%2,%3}, {%4,%5,%6,%7}, {%8,%9}, {%0,%1,%2,%3};\n"
                 : "+f"(c[0]), "+f"(c[1]), "+f"(c[2]), "+f"(c[3])
                 : "r"(a0), "r"(a1), "r"(a2), "r"(a3), "r"(b0), "r"(b1));
}
__device__ __forceinline__ uint32_t pack_bf2(float a, float b) {
    __nv_bfloat162 p = __floats2bfloat162_rn(a, b);
    return *(uint32_t*)&p;
}
__device__ __forceinline__ void cp16(uint32_t dst, const void* src) {
    asm volatile("cp.async.ca.shared.global [%0], [%1], 16;\n" :: "r"(dst), "l"(src));
}
#define CP_COMMIT() asm volatile("cp.async.commit_group;\n" ::: "memory")

// ============ full-K resident tiles (pitch 136) ============================
#define FP 136
#define TILE_B (128 * FP * 2)   // 34816 bytes

__device__ __forceinline__ void load_w136(uint32_t dst, const __nv_bfloat16* src,
                                          int ldk, int tid)
{
    #pragma unroll
    for (int i = 0; i < 8; i++) {
        int ch = i * 256 + tid;
        int r = ch >> 4, c8 = ch & 15;
        cp16(dst + (uint32_t)(r * FP + c8 * 8) * 2, src + (size_t)r * ldk + c8 * 8);
    }
}

// inline LayerNorm: 128 rows, warp per row, bf16 smem out
__device__ __forceinline__ void ln_to_smem(const float* __restrict__ in, uint32_t dstB,
    const float* __restrict__ g, const float* __restrict__ b,
    int blockM, int gather, int tid)
{
    int warp = tid >> 5, lane = tid & 31;
    float4 gg = *(const float4*)(g + lane * 4);
    float4 bb = *(const float4*)(b + lane * 4);
    #pragma unroll
    for (int i = 0; i < 16; i++) {
        int r = i * 8 + warp;
        int row = blockM + r;
        int src = gather ? win_to_img(row) : row;
        float4 v = *(const float4*)(in + (size_t)src * CC + lane * 4);
        float s = v.x + v.y + v.z + v.w;
        #pragma unroll
        for (int o = 16; o; o >>= 1) s += __shfl_xor_sync(~0u, s, o);
        float mean = s * (1.f / CC);
        float dx = v.x - mean, dy = v.y - mean, dz = v.z - mean, dw = v.w - mean;
        float vv = dx*dx + dy*dy + dz*dz + dw*dw;
        #pragma unroll
        for (int o = 16; o; o >>= 1) vv += __shfl_xor_sync(~0u, vv, o);
        float rstd = rsqrtf(vv * (1.f / CC) + 1e-5f);
        uint32_t p0 = pack_bf2(dx * rstd * gg.x + bb.x, dy * rstd * gg.y + bb.y);
        uint32_t p1 = pack_bf2(dz * rstd * gg.z + bb.z, dw * rstd * gg.w + bb.w);
        asm volatile("st.shared.v2.b32 [%0], {%1,%2};" ::
                     "r"(dstB + (uint32_t)(r * FP + lane * 4) * 2), "r"(p0), "r"(p1) : "memory");
    }
}

// full-K (128) warp-tile MMA on pitch-136 smem: 32x64 warp tile
__device__ __forceinline__ void wtile_mma(uint32_t aB, uint32_t bB, float acc[2][8][4],
                                          int warp_m, int warp_n, int rowin, int kin)
{
    #pragma unroll
    for (int ks = 0; ks < 128; ks += 16) {
        uint32_t af[2][4], bfr[4][4];
        #pragma unroll
        for (int mi = 0; mi < 2; mi++) {
            int m = warp_m * 32 + mi * 16 + rowin;
            ldsm4(af[mi][0], af[mi][1], af[mi][2], af[mi][3],
                  aB + (uint32_t)(m * FP + ks + kin) * 2);
        }
        #pragma unroll
        for (int np = 0; np < 4; np++) {
            int n = warp_n * 64 + np * 16 + rowin;
            ldsm4(bfr[np][0], bfr[np][1], bfr[np][2], bfr[np][3],
                  bB + (uint32_t)(n * FP + ks + kin) * 2);
        }
        #pragma unroll
        for (int mi = 0; mi < 2; mi++)
            #pragma unroll
            for (int np = 0; np < 4; np++)
                #pragma unroll
                for (int sub = 0; sub < 2; sub++)
                    mma16816(acc[mi][np * 2 + sub],
                             af[mi][0], af[mi][1], af[mi][2], af[mi][3],
                             bfr[np][sub], bfr[np][sub + 2]);
    }
}

// ---------------- fused LN1 + QKV GEMM (R11-validated) ---------------------
#define SM_QKV (3 * TILE_B)
__global__ void __launch_bounds__(256, 2) qkv_fused(
    const float* __restrict__ x, const __nv_bfloat16* __restrict__ wq,
    const float* __restrict__ ln_g, const float* __restrict__ ln_b,
    const float* __restrict__ bq, __nv_bfloat16* __restrict__ qkvb)
{
    extern __shared__ __align__(16) char smem[];
    uint32_t aB = (uint32_t)__cvta_generic_to_shared(smem);
    uint32_t wB = aB + TILE_B;
    int tid = threadIdx.x, lane = tid & 31, warp = tid >> 5;
    int warp_m = warp & 3, warp_n = warp >> 2;
    int blockM = blockIdx.x * 128;

    load_w136(wB, wq, CC, tid);                     CP_COMMIT();
    load_w136(wB + TILE_B, wq + 128 * CC, CC, tid); CP_COMMIT();
    ln_to_smem(x, aB, ln_g, ln_b, blockM, 1, tid);

    int grp   = lane >> 3;
    int rowin = (lane & 7) | ((grp & 1) << 3);
    int kin   = (grp >> 1) << 3;

    #pragma unroll
    for (int t = 0; t < 3; t++) {
        if (t < 2) asm volatile("cp.async.wait_group 1;" ::: "memory");
        else       asm volatile("cp.async.wait_group 0;" ::: "memory");
        __syncthreads();

        float acc[2][8][4];
        #pragma unroll
        for (int i = 0; i < 2; i++)
            #pragma unroll
            for (int j = 0; j < 8; j++)
                #pragma unroll
                for (int k = 0; k < 4; k++) acc[i][j][k] = 0.f;

        wtile_mma(aB, wB + (t & 1) * TILE_B, acc, warp_m, warp_n, rowin, kin);
        __syncthreads();
        if (t == 0) { load_w136(wB, wq + 256 * CC, CC, tid); CP_COMMIT(); }

        #pragma unroll
        for (int mi = 0; mi < 2; mi++)
            #pragma unroll
            for (int h2 = 0; h2 < 2; h2++) {
                int r = blockM + warp_m * 32 + mi * 16 + (lane >> 2) + h2 * 8;
                #pragma unroll
                for (int ni = 0; ni < 8; ni++) {
                    int cl = warp_n * 64 + ni * 8 + (lane & 3) * 2;
                    int c = t * 128 + cl;
                    float v0 = acc[mi][ni][h2 * 2 + 0] + bq[c];
                    float v1 = acc[mi][ni][h2 * 2 + 1] + bq[c + 1];
                    *(__nv_bfloat162*)(qkvb + (size_t)r * (3 * CC) + c) =
                        __floats2bfloat162_rn(v0, v1);
                }
            }
    }
}

// ---------------- fc1: A-resident, 4 in-CTA N-tiles, GELU epilogue ---------
#define SM_FC1 (3 * TILE_B)
__global__ void __launch_bounds__(256, 2) fc1_fused(
    const __nv_bfloat16* __restrict__ A, const __nv_bfloat16* __restrict__ w1,
    const float* __restrict__ b1, __nv_bfloat16* __restrict__ act)
{
    extern __shared__ __align__(16) char smem[];
    uint32_t aB = (uint32_t)__cvta_generic_to_shared(smem);
    uint32_t wB = aB + TILE_B;
    int tid = threadIdx.x, lane = tid & 31, warp = tid >> 5;
    int warp_m = warp & 3, warp_n = warp >> 2;
    int blockM = (gridDim.x - 1 - blockIdx.x) * 128;   // reversed

    load_w136(aB, A + (size_t)blockM * CC, CC, tid);
    load_w136(wB, w1, CC, tid);                     CP_COMMIT();
    load_w136(wB + TILE_B, w1 + 128 * CC, CC, tid); CP_COMMIT();

    int grp   = lane >> 3;
    int rowin = (lane & 7) | ((grp & 1) << 3);
    int kin   = (grp >> 1) << 3;

    #pragma unroll
    for (int t = 0; t < 4; t++) {
        if (t < 3) asm volatile("cp.async.wait_group 1;" ::: "memory");
        else       asm volatile("cp.async.wait_group 0;" ::: "memory");
        __syncthreads();

        float acc[2][8][4];
        #pragma unroll
        for (int i = 0; i < 2; i++)
            #pragma unroll
            for (int j = 0; j < 8; j++)
                #pragma unroll
                for (int k = 0; k < 4; k++) acc[i][j][k] = 0.f;

        wtile_mma(aB, wB + (t & 1) * TILE_B, acc, warp_m, warp_n, rowin, kin);
        __syncthreads();
        if (t + 2 < 4) {
            load_w136(wB + (t & 1) * TILE_B, w1 + (size_t)(t + 2) * 128 * CC, CC, tid);
            CP_COMMIT();
        }

        #pragma unroll
        for (int mi = 0; mi < 2; mi++)
            #pragma unroll
            for (int h2 = 0; h2 < 2; h2++) {
                int r = blockM + warp_m * 32 + mi * 16 + (lane >> 2) + h2 * 8;
                #pragma unroll
                for (int ni = 0; ni < 8; ni++) {
                    int cl = warp_n * 64 + ni * 8 + (lane & 3) * 2;
                    int c = t * 128 + cl;
                    float v0 = acc[mi][ni][h2 * 2 + 0] + b1[c];
                    float v1 = acc[mi][ni][h2 * 2 + 1] + b1[c + 1];
                    v0 = 0.5f * v0 * (1.f + erff(v0 * 0.70710678118654752f));
                    v1 = 0.5f * v1 * (1.f + erff(v1 * 0.70710678118654752f));
                    *(__nv_bfloat162*)(act + (size_t)r * MLPH + c) =
                        __floats2bfloat162_rn(v0, v1);
                }
            }
    }
}

// ============ fc2: 3-slot deep pipeline (KC=32), +residual epilogue ========
#define KC      32
#define SPITCH  40
#define ASLOT   (128 * SPITCH * 2)       // 10240 bytes per operand slot
#define SM_FC2  (6 * ASLOT)              // 3 A-slots + 3 B-slots = 61440

__global__ void __launch_bounds__(256, 2) fc2_gemm(
    const __nv_bfloat16* __restrict__ A, const __nv_bfloat16* __restrict__ W,
    const float* __restrict__ bias, float* __restrict__ out,
    const float* __restrict__ x1)
{
    const int K = MLPH, N = CC;
    extern __shared__ __align__(16) char smem[];
    uint32_t aBase = (uint32_t)__cvta_generic_to_shared(smem);
    uint32_t bBase = aBase + 3 * ASLOT;

    int tid = threadIdx.x, lane = tid & 31, warp = tid >> 5;
    int warp_m = warp & 3, warp_n = warp >> 2;
    int blockM = blockIdx.x * 128;

    float acc[2][8][4];
    #pragma unroll
    for (int i = 0; i < 2; i++)
        #pragma unroll
        for (int j = 0; j < 8; j++)
            #pragma unroll
            for (int k = 0; k < 4; k++) acc[i][j][k] = 0.f;

    int grp   = lane >> 3;
    int rowin = (lane & 7) | ((grp & 1) << 3);
    int kin   = (grp >> 1) << 3;

    int r8 = tid >> 2, k8 = (tid & 3) * 8;
    int r8b = (tid + 256) >> 2, k8b = ((tid + 256) & 3) * 8;

    // prologue: prefetch slots 0,1
    #pragma unroll
    for (int p = 0; p < 2; p++) {
        int kt = p * KC;
        uint32_t aS = aBase + p * ASLOT, bS = bBase + p * ASLOT;
        cp16(aS + (r8  * SPITCH + k8 ) * 2, A + (size_t)(blockM + r8 ) * K + kt + k8 );
        cp16(aS + (r8b * SPITCH + k8b) * 2, A + (size_t)(blockM + r8b) * K + kt + k8b);
        cp16(bS + (r8  * SPITCH + k8 ) * 2, W + (size_t)r8  * K + kt + k8 );
        cp16(bS + (r8b * SPITCH + k8b) * 2, W + (size_t)r8b * K + kt + k8b);
        CP_COMMIT();
    }

    const int nk = K / KC;   // 16
    for (int s = 0; s < nk; s++) {
        if (s < nk - 1) asm volatile("cp.async.wait_group 1;" ::: "memory");
        else            asm volatile("cp.async.wait_group 0;" ::: "memory");
        __syncthreads();
        // issue s+2 into slot (s+2)%3 (last read at iter s-1; safe past sync)
        if (s + 2 < nk) {
            int slot = (s + 2) % 3, kt = (s + 2) * KC;
            uint32_t aS = aBase + slot * ASLOT, bS = bBase + slot * ASLOT;
            cp16(aS + (r8  * SPITCH + k8 ) * 2, A + (size_t)(blockM + r8 ) * K + kt + k8 );
            cp16(aS + (r8b * SPITCH + k8b) * 2, A + (size_t)(blockM + r8b) * K + kt + k8b);
            cp16(bS + (r8  * SPITCH + k8 ) * 2, W + (size_t)r8  * K + kt + k8 );
            cp16(bS + (r8b * SPITCH + k8b) * 2, W + (size_t)r8b * K + kt + k8b);
            CP_COMMIT();
        }

        uint32_t aS = aBase + (s % 3) * ASLOT;
        uint32_t bS = bBase + (s % 3) * ASLOT;
        #pragma unroll
        for (int ks = 0; ks < KC; ks += 16) {
            uint32_t af[2][4], bfr[4][4];
            #pragma unroll
            for (int mi = 0; mi < 2; mi++) {
                int m = warp_m * 32 + mi * 16 + rowin;
                ldsm4(af[mi][0], af[mi][1], af[mi][2], af[mi][3],
                      aS + (uint32_t)(m * SPITCH + ks + kin) * 2);
            }
            #pragma unroll
            for (int np = 0; np < 4; np++) {
                int n = warp_n * 64 + np * 16 + rowin;
                ldsm4(bfr[np][0], bfr[np][1], bfr[np][2], bfr[np][3],
                      bS + (uint32_t)(n * SPITCH + ks + kin) * 2);
            }
            #pragma unroll
            for (int mi = 0; mi < 2; mi++)
                #pragma unroll
                for (int np = 0; np < 4; np++)
                    #pragma unroll
                    for (int sub = 0; sub < 2; sub++)
                        mma16816(acc[mi][np * 2 + sub],
                                 af[mi][0], af[mi][1], af[mi][2], af[mi][3],
                                 bfr[np][sub], bfr[np][sub + 2]);
        }
    }

    int rowBase = blockM + warp_m * 32;
    int colBase = warp_n * 64;
    #pragma unroll
    for (int mi = 0; mi < 2; mi++) {
        #pragma unroll
        for (int h2 = 0; h2 < 2; h2++) {
            int r = rowBase + mi * 16 + (lane >> 2) + h2 * 8;
            #pragma unroll
            for (int ni = 0; ni < 8; ni++) {
                int c = colBase + ni * 8 + (lane & 3) * 2;
                float2 bi = *(const float2*)(bias + c);
                float2 e = *(const float2*)(x1 + (size_t)r * N + c);
                out[(size_t)r * N + c]     = e.x + bi.x + acc[mi][ni][h2 * 2 + 0];
                out[(size_t)r * N + c + 1] = e.y + bi.y + acc[mi][ni][h2 * 2 + 1];
            }
        }
    }
}

// ---------------- proj GEMM + scatter + residual + fused LN2 (R12) ---------
#define STAGEB (128 * SPITCH * 2)
#define XBUF_OFF (4 * STAGEB)
#define SM_PROJLN (XBUF_OFF + 128 * 136 * 2)

__global__ void __launch_bounds__(256, 2) proj_ln(
    const __nv_bfloat16* __restrict__ A, const __nv_bfloat16* __restrict__ W,
    const float* __restrict__ bias, float* __restrict__ x1out,
    const float* __restrict__ xres,
    const float* __restrict__ ln_g, const float* __restrict__ ln_b,
    __nv_bfloat16* __restrict__ hwin)
{
    extern __shared__ __align__(16) char smem[];
    const int K = CC;
    uint32_t aBase = (uint32_t)__cvta_generic_to_shared(smem);
    uint32_t bBase = aBase + 2 * STAGEB;
    __nv_bfloat16* xbuf = (__nv_bfloat16*)(smem + XBUF_OFF);

    int tid = threadIdx.x, lane = tid & 31, warp = tid >> 5;
    int warp_m = warp & 3, warp_n = warp >> 2;
    int blockM = blockIdx.x * 128;

    float acc[2][8][4];
    #pragma unroll
    for (int i = 0; i < 2; i++)
        #pragma unroll
        for (int j = 0; j < 8; j++)
            #pragma unroll
            for (int k = 0; k < 4; k++) acc[i][j][k] = 0.f;

    int grp   = lane >> 3;
    int rowin = (lane & 7) | ((grp & 1) << 3);
    int kin   = (grp >> 1) << 3;

    int r8 = tid >> 2, k8 = (tid & 3) * 8;
    int r8b = (tid + 256) >> 2, k8b = ((tid + 256) & 3) * 8;

    cp16(aBase + (r8  * SPITCH + k8 ) * 2, A + (size_t)(blockM + r8 ) * K + k8 );
    cp16(aBase + (r8b * SPITCH + k8b) * 2, A + (size_t)(blockM + r8b) * K + k8b);
    cp16(bBase + (r8  * SPITCH + k8 ) * 2, W + (size_t)r8  * K + k8 );
    cp16(bBase + (r8b * SPITCH + k8b) * 2, W + (size_t)r8b * K + k8b);
    asm volatile("cp.async.commit_group;\n");

    int nk = K >> 5;
    for (int s = 0; s < nk; s++) {
        if (s + 1 < nk) {
            int kt = (s + 1) << 5;
            uint32_t ao = aBase + ((s + 1) & 1) * STAGEB;
            uint32_t bo = bBase + ((s + 1) & 1) * STAGEB;
            cp16(ao + (r8  * SPITCH + k8 ) * 2, A + (size_t)(blockM + r8 ) * K + kt + k8 );
            cp16(ao + (r8b * SPITCH + k8b) * 2, A + (size_t)(blockM + r8b) * K + kt + k8b);
            cp16(bo + (r8  * SPITCH + k8 ) * 2, W + (size_t)r8  * K + kt + k8 );
            cp16(bo + (r8b * SPITCH + k8b) * 2, W + (size_t)r8b * K + kt + k8b);
            asm volatile("cp.async.commit_group;\n");
            asm volatile("cp.async.wait_group 1;\n");
        } else {
            asm volatile("cp.async.wait_group 0;\n");
        }
        __syncthreads();

        uint32_t aS = aBase + (s & 1) * STAGEB;
        uint32_t bS = bBase + (s & 1) * STAGEB;
        #pragma unroll
        for (int ks = 0; ks < KC; ks += 16) {
            uint32_t af[2][4], bfr[4][4];
            #pragma unroll
            for (int mi = 0; mi < 2; mi++) {
                int m = warp_m * 32 + mi * 16 + rowin;
                ldsm4(af[mi][0], af[mi][1], af[mi][2], af[mi][3],
                      aS + (uint32_t)(m * SPITCH + ks + kin) * 2);
            }
            #pragma unroll
            for (int np = 0; np < 4; np++) {
                int n = warp_n * 64 + np * 16 + rowin;
                ldsm4(bfr[np][0], bfr[np][1], bfr[np][2], bfr[np][3],
                      bS + (uint32_t)(n * SPITCH + ks + kin) * 2);
            }
            #pragma unroll
            for (int mi = 0; mi < 2; mi++)
                #pragma unroll
                for (int np = 0; np < 4; np++)
                    #pragma unroll
                    for (int sub = 0; sub < 2; sub++)
                        mma16816(acc[mi][np * 2 + sub],
                                 af[mi][0], af[mi][1], af[mi][2], af[mi][3],
                                 bfr[np][sub], bfr[np][sub + 2]);
        }
        __syncthreads();
    }

    #pragma unroll
    for (int mi = 0; mi < 2; mi++)
        #pragma unroll
        for (int h2 = 0; h2 < 2; h2++) {
            int rl = warp_m * 32 + mi * 16 + (lane >> 2) + h2 * 8;
            size_t orow = (size_t)win_to_img(blockM + rl);
            #pragma unroll
            for (int ni = 0; ni < 8; ni++) {
                int c = warp_n * 64 + ni * 8 + (lane & 3) * 2;
                float2 bi = *(const float2*)(bias + c);
                float2 e = *(const float2*)(xres + orow * CC + c);
                float v0 = e.x + bi.x + acc[mi][ni][h2 * 2 + 0];
                float v1 = e.y + bi.y + acc[mi][ni][h2 * 2 + 1];
                x1out[orow * CC + c]     = v0;
                x1out[orow * CC + c + 1] = v1;
                *(__nv_bfloat162*)(xbuf + rl * 136 + c) = __floats2bfloat162_rn(v0, v1);
            }
        }
    __syncthreads();

    {
        float4 gg = *(const float4*)(ln_g + lane * 4);
        float4 bb = *(const float4*)(ln_b + lane * 4);
        #pragma unroll
        for (int i = 0; i < 16; i++) {
            int rl = i * 8 + warp;
            const __nv_bfloat16* row = xbuf + rl * 136 + lane * 4;
            __nv_bfloat162 q0 = *(const __nv_bfloat162*)(row);
            __nv_bfloat162 q1 = *(const __nv_bfloat162*)(row + 2);
            float vx = __bfloat162float(q0.x), vy = __bfloat162float(q0.y);
            float vz = __bfloat162float(q1.x), vw = __bfloat162float(q1.y);
            float s = vx + vy + vz + vw;
            #pragma unroll
            for (int o = 16; o; o >>= 1) s += __shfl_xor_sync(~0u, s, o);
            float mean = s * (1.f / CC);
            float dx = vx - mean, dy = vy - mean, dz = vz - mean, dw = vw - mean;
            float vv = dx*dx + dy*dy + dz*dz + dw*dw;
            #pragma unroll
            for (int o = 16; o; o >>= 1) vv += __shfl_xor_sync(~0u, vv, o);
            float rstd = rsqrtf(vv * (1.f / CC) + 1e-5f);
            size_t orow = (size_t)win_to_img(blockM + rl);
            __nv_bfloat162 p0 = __floats2bfloat162_rn(dx * rstd * gg.x + bb.x, dy * rstd * gg.y + bb.y);
            __nv_bfloat162 p1 = __floats2bfloat162_rn(dz * rstd * gg.z + bb.z, dw * rstd * gg.w + bb.w);
            *(__nv_bfloat162*)(hwin + orow * CC + lane * 4)     = p0;
            *(__nv_bfloat162*)(hwin + orow * CC + lane * 4 + 2) = p1;
        }
    }
}

// ---------------- tensor-core window attention (bm bf16, reversed) ---------
__global__ void __launch_bounds__(128) attn_tc(
    const __nv_bfloat16* __restrict__ qkv, const __nv_bfloat16* __restrict__ bm,
    __nv_bfloat16* __restrict__ obuf)
{
    int w = (TOTW - 1) - (blockIdx.x >> 2);
    int h = blockIdx.x & 3;
    int tid = threadIdx.x, lane = tid & 31, warp = tid >> 5;

    __shared__ __align__(16) __nv_bfloat16 qs[64 * 40];
    __shared__ __align__(16) __nv_bfloat16 ks[64 * 40];
    __shared__ __align__(16) __nv_bfloat16 vsn[64 * 40];

    size_t base = (size_t)w * NTOK * (3 * CC) + h * HD;

    #pragma unroll
    for (int i = tid; i < 256; i += 128) {
        int n = i >> 2, j = i & 3;
        uint4 qv = {0,0,0,0}, kv = {0,0,0,0}, vv = {0,0,0,0};
        if (n < NTOK) {
            const __nv_bfloat16* src = qkv + base + (size_t)n * (3 * CC) + j * 8;
            qv = *(const uint4*)(src);
            kv = *(const uint4*)(src + CC);
            vv = *(const uint4*)(src + 2 * CC);
        }
        *(uint4*)&qs [n * 40 + j * 8] = qv;
        *(uint4*)&ks [n * 40 + j * 8] = kv;
        *(uint4*)&vsn[n * 40 + j * 8] = vv;
    }
    __syncthreads();

    int grp   = lane >> 3;
    int rowin = (lane & 7) | ((grp & 1) << 3);
    int kin   = (grp >> 1) << 3;
    uint32_t qB = (uint32_t)__cvta_generic_to_shared(qs);
    uint32_t kB = (uint32_t)__cvta_generic_to_shared(ks);
    uint32_t vB = (uint32_t)__cvta_generic_to_shared(vsn);

    float acc[8][4];
    #pragma unroll
    for (int i = 0; i < 8; i++)
        #pragma unroll
        for (int j = 0; j < 4; j++) acc[i][j] = 0.f;

    int r0 = warp * 16;
    #pragma unroll
    for (int kk = 0; kk < 32; kk += 16) {
        uint32_t af[4];
        ldsm4(af[0], af[1], af[2], af[3],
              qB + (uint32_t)((r0 + rowin) * 40 + kk + kin) * 2);
        #pragma unroll
        for (int np = 0; np < 4; np++) {
            uint32_t bv[4];
            ldsm4(bv[0], bv[1], bv[2], bv[3],
                  kB + (uint32_t)((np * 16 + rowin) * 40 + kk + kin) * 2);
            mma16816(acc[np * 2 + 0], af[0], af[1], af[2], af[3], bv[0], bv[2]);
            mma16816(acc[np * 2 + 1], af[0], af[1], af[2], af[3], bv[1], bv[3]);
        }
    }

    int rA = r0 + (lane >> 2);
    int widx = w & 63;
    int wt = (((widx >> 3) == 7) ? 2 : 0) | (((widx & 7) == 7) ? 1 : 0);
    const __nv_bfloat16* bmA = bm + (((wt << 2) | h) << 12) + rA * 64;
    const __nv_bfloat16* bmB = bmA + 8 * 64;
    int mcol = (lane & 3) * 2;
    #pragma unroll
    for (int nt = 0; nt < 8; nt++) {
        float2 bA = __bfloat1622float2(*(const __nv_bfloat162*)(bmA + nt * 8 + mcol));
        float2 bB = __bfloat1622float2(*(const __nv_bfloat162*)(bmB + nt * 8 + mcol));
        acc[nt][0] += bA.x; acc[nt][1] += bA.y;
        acc[nt][2] += bB.x; acc[nt][3] += bB.y;
    }

    float mA = -1e30f, mB = -1e30f;
    #pragma unroll
    for (int nt = 0; nt < 8; nt++) {
        mA = fmaxf(mA, fmaxf(acc[nt][0], acc[nt][1]));
        mB = fmaxf(mB, fmaxf(acc[nt][2], acc[nt][3]));
    }
    mA = fmaxf(mA, __shfl_xor_sync(~0u, mA, 1));
    mA = fmaxf(mA, __shfl_xor_sync(~0u, mA, 2));
    mB = fmaxf(mB, __shfl_xor_sync(~0u, mB, 1));
    mB = fmaxf(mB, __shfl_xor_sync(~0u, mB, 2));
    float sA = 0.f, sB = 0.f;
    #pragma unroll
    for (int nt = 0; nt < 8; nt++) {
        acc[nt][0] = __expf(acc[nt][0] - mA);
        acc[nt][1] = __expf(acc[nt][1] - mA);
        acc[nt][2] = __expf(acc[nt][2] - mB);
        acc[nt][3] = __expf(acc[nt][3] - mB);
        sA += acc[nt][0] + acc[nt][1];
        sB += acc[nt][2] + acc[nt][3];
    }
    sA += __shfl_xor_sync(~0u, sA, 1);
    sA += __shfl_xor_sync(~0u, sA, 2);
    sB += __shfl_xor_sync(~0u, sB, 1);
    sB += __shfl_xor_sync(~0u, sB, 2);
    float invA = 1.f / sA, invB = 1.f / sB;

    uint32_t pa[4][4];
    #pragma unroll
    for (int j = 0; j < 4; j++) {
        pa[j][0] = pack_bf2(acc[2*j][0]   * invA, acc[2*j][1]   * invA);
        pa[j][1] = pack_bf2(acc[2*j][2]   * invB, acc[2*j][3]   * invB);
        pa[j][2] = pack_bf2(acc[2*j+1][0] * invA, acc[2*j+1][1] * invA);
        pa[j][3] = pack_bf2(acc[2*j+1][2] * invB, acc[2*j+1][3] * invB);
    }

    float oacc[4][4];
    #pragma unroll
    for (int i = 0; i < 4; i++)
        #pragma unroll
        for (int j = 0; j < 4; j++) oacc[i][j] = 0.f;

    int vrow = (lane & 7) | ((grp >> 1) << 3);
    int vcol = (grp & 1) * 8;
    #pragma unroll
    for (int j = 0; j < 4; j++) {
        #pragma unroll
        for (int dg = 0; dg < 2; dg++) {
            uint32_t bv[4];
            ldsm4t(bv[0], bv[1], bv[2], bv[3],
                   vB + (uint32_t)((j * 16 + vrow) * 40 + dg * 16 + vcol) * 2);
            mma16816(oacc[dg * 2 + 0], pa[j][0], pa[j][1], pa[j][2], pa[j][3], bv[0], bv[2]);
            mma16816(oacc[dg * 2 + 1], pa[j][0], pa[j][1], pa[j][2], pa[j][3], bv[1], bv[3]);
        }
    }

    int rB = rA + 8;
    #pragma unroll
    for (int nd = 0; nd < 4; nd++) {
        int c = h * HD + nd * 8 + (lane & 3) * 2;
        if (rA < NTOK)
            *(__nv_bfloat162*)(obuf + ((size_t)w * NTOK + rA) * CC + c) =
                __floats2bfloat162_rn(oacc[nd][0], oacc[nd][1]);
        if (rB < NTOK)
            *(__nv_bfloat162*)(obuf + ((size_t)w * NTOK + rB) * CC + c) =
                __floats2bfloat162_rn(oacc[nd][2], oacc[nd][3]);
    }
}

// ---------------- launch --------------------------------------------------
extern "C" void kernel_launch(void* const* d_in, const int* in_sizes, int n_in,
                              void* d_out, int out_size)
{
    const float* x      = (const float*)d_in[0];
    const float* ln1_g  = (const float*)d_in[1];
    const float* ln1_b  = (const float*)d_in[2];
    const float* qkv_w  = (const float*)d_in[3];
    const float* qkv_b  = (const float*)d_in[4];
    const float* rpb    = (const float*)d_in[5];
    const float* proj_w = (const float*)d_in[6];
    const float* proj_b = (const float*)d_in[7];
    const float* ln2_g  = (const float*)d_in[8];
    const float* ln2_b  = (const float*)d_in[9];
    const float* fc1_w  = (const float*)d_in[10];
    const float* fc1_b  = (const float*)d_in[11];
    const float* fc2_w  = (const float*)d_in[12];
    const float* fc2_b  = (const float*)d_in[13];
    float* out = (float*)d_out;

    __nv_bfloat16 *hwin, *qkvb, *obuf, *act, *wq, *wp, *wf1, *wf2, *bm;
    float *x1, *bq;
    cudaGetSymbolAddress((void**)&hwin, g_hwin);
    cudaGetSymbolAddress((void**)&qkvb, g_qkv);
    cudaGetSymbolAddress((void**)&obuf, g_obuf);
    cudaGetSymbolAddress((void**)&x1,   g_x1);
    cudaGetSymbolAddress((void**)&act,  g_act);
    cudaGetSymbolAddress((void**)&wq,   g_wq);
    cudaGetSymbolAddress((void**)&wp,   g_wp);
    cudaGetSymbolAddress((void**)&wf1,  g_wf1);
    cudaGetSymbolAddress((void**)&wf2,  g_wf2);
    cudaGetSymbolAddress((void**)&bq,   g_bq);
    cudaGetSymbolAddress((void**)&bm,   g_bm);

    static int init_done = 0;
    if (!init_done) {
        cudaFuncSetAttribute(qkv_fused, cudaFuncAttributeMaxDynamicSharedMemorySize, SM_QKV);
        cudaFuncSetAttribute(fc1_fused, cudaFuncAttributeMaxDynamicSharedMemorySize, SM_FC1);
        cudaFuncSetAttribute(fc2_gemm, cudaFuncAttributeMaxDynamicSharedMemorySize, SM_FC2);
        cudaFuncSetAttribute(proj_ln, cudaFuncAttributeMaxDynamicSharedMemorySize, SM_PROJLN);
        init_done = 1;
    }

    // 0) weight conversions + fused bias/mask table (one launch)
    f2bf_all<<<768, 256>>>(qkv_w, proj_w, fc1_w, fc2_w, qkv_b, rpb,
                           wq, wp, wf1, wf2, bq, bm);

    // 1) LN1 + shift/gather + QKV projection (fused)
    qkv_fused<<<MROWS / 128, 256, SM_QKV>>>(x, wq, ln1_g, ln1_b, bq, qkvb);
    // 2) tensor-core window attention
    attn_tc<<<TOTW * NH, 128>>>(qkvb, bm, obuf);
    // 3) proj + scatter + residual + fused LN2 -> x1 fp32 + hwin bf16
    proj_ln<<<MROWS / 128, 256, SM_PROJLN>>>(obuf, wp, proj_b, x1, x, ln2_g, ln2_b, hwin);
    // 4) fc1 + GELU
    fc1_fused<<<MROWS / 128, 256, SM_FC1>>>(hwin, wf1, fc1_b, act);
    // 5) fc2 + residual (3-slot deep pipeline) -> final fp32
    fc2_gemm<<<MROWS / 128, 256, SM_FC2>>>(act, wf2, fc2_b, out, x1);
}